// round 12
// baseline (speedup 1.0000x reference)
#include <cuda_runtime.h>
#include <cuda_fp16.h>
#include <math_constants.h>
#include <cstdint>

// Problem constants (match reference)
#define D         128
#define N_SRC_MAX 50000
#define N_DST_MAX 50000
#define E_MAX     1600000
#define INV_SCALE 0.25f          // 1/sqrt(128/8) = 1/4

// ---------------- scratch (no allocations allowed) ----------------
__device__ __align__(128) float  g_Q[N_DST_MAX * D];
__device__ __align__(128) float  g_K[N_SRC_MAX * D];
__device__ __align__(128) __half g_Vh[N_SRC_MAX * D];
__device__ __align__(128) int    g_count[N_DST_MAX];
__device__ __align__(128) int    g_start[N_DST_MAX + 1];
__device__ __align__(128) int    g_cursor[N_DST_MAX];
__device__ __align__(128) int    g_perm_src[E_MAX];
__device__ __align__(128) int    g_bsum[128];
__device__ int g_is64;

// ---------------- helpers ----------------
__device__ __forceinline__ int load_idx(const void* p, int i) {
    if (g_is64) return (int)((const long long*)p)[i];
    return ((const int*)p)[i];
}
__device__ __forceinline__ void fma2(unsigned long long& d,
                                     unsigned long long a, unsigned long long b) {
    asm("fma.rn.f32x2 %0, %1, %2, %0;" : "+l"(d) : "l"(a), "l"(b));
}
__device__ __forceinline__ unsigned long long pack2(float x) {
    unsigned long long r;
    asm("mov.b64 %0, {%1, %1};" : "=l"(r) : "f"(x));
    return r;
}

// ---------------- dtype detection ----------------
__global__ void detect_idx_kernel(const void* src_idx, const void* dst_idx,
                                  int n_src, int n_dst, int E) {
    if (threadIdx.x == 0) g_is64 = 1;
    __syncthreads();
    int i = threadIdx.x;
    int limit = (E / 2 < 64) ? E / 2 : 64;
    if (i < limit) {
        long long s = ((const long long*)src_idx)[i];
        long long d = ((const long long*)dst_idx)[i];
        bool ok = (s >= 0 && s < n_src && d >= 0 && d < n_dst);
        if (!ok) atomicExch(&g_is64, 0);
    }
}

__global__ void zero_counts_kernel(int n_dst) {
    int i = blockIdx.x * blockDim.x + threadIdx.x;
    if (i < n_dst) g_count[i] = 0;
}

__global__ __launch_bounds__(256) void hist_kernel(const void* __restrict__ dst_idx, int E) {
    int i = blockIdx.x * blockDim.x + threadIdx.x;
    if (i < E) atomicAdd(&g_count[load_idx(dst_idx, i)], 1);
}

// ---------------- parallel exclusive scan (3 kernels) ----------------
__global__ __launch_bounds__(256) void scan_bsum_kernel(int n_dst) {
    int t = threadIdx.x;
    int base = blockIdx.x * 1024 + t * 4;
    int v = 0;
    #pragma unroll
    for (int j = 0; j < 4; j++) {
        int i = base + j;
        if (i < n_dst) v += g_count[i];
    }
    #pragma unroll
    for (int off = 16; off; off >>= 1) v += __shfl_xor_sync(0xFFFFFFFFu, v, off);
    __shared__ int ws[8];
    if ((t & 31) == 0) ws[t >> 5] = v;
    __syncthreads();
    if (t < 8) {
        int u = ws[t];
        #pragma unroll
        for (int off = 4; off; off >>= 1) u += __shfl_xor_sync(0xFFu, u, off);
        if (t == 0) g_bsum[blockIdx.x] = u;
    }
}

__global__ __launch_bounds__(128) void scan_top_kernel(int nblocks) {
    __shared__ int s[128];
    int t = threadIdx.x;
    s[t] = (t < nblocks) ? g_bsum[t] : 0;
    __syncthreads();
    for (int off = 1; off < 128; off <<= 1) {
        int v = (t >= off) ? s[t - off] : 0;
        __syncthreads();
        s[t] += v;
        __syncthreads();
    }
    int excl = (t == 0) ? 0 : s[t - 1];
    if (t < nblocks) g_bsum[t] = excl;
}

__global__ __launch_bounds__(256) void scan_apply_kernel(int n_dst, int E) {
    __shared__ int ws[8];
    int t = threadIdx.x;
    int lane = t & 31, wid = t >> 5;
    int base = blockIdx.x * 1024 + t * 4;
    int c[4];
    int s_local = 0;
    #pragma unroll
    for (int j = 0; j < 4; j++) {
        int i = base + j;
        c[j] = (i < n_dst) ? g_count[i] : 0;
        s_local += c[j];
    }
    int v = s_local;
    #pragma unroll
    for (int off = 1; off < 32; off <<= 1) {
        int u = __shfl_up_sync(0xFFFFFFFFu, v, off);
        if (lane >= off) v += u;
    }
    if (lane == 31) ws[wid] = v;
    __syncthreads();
    if (t < 8) {
        int u = ws[t];
        #pragma unroll
        for (int off = 1; off < 8; off <<= 1) {
            int x = __shfl_up_sync(0xFFu, u, off);
            if (t >= off) u += x;
        }
        ws[t] = u;
    }
    __syncthreads();
    int run = v - s_local + (wid ? ws[wid - 1] : 0) + g_bsum[blockIdx.x];
    #pragma unroll
    for (int j = 0; j < 4; j++) {
        int i = base + j;
        if (i < n_dst) {
            g_start[i]  = run;
            g_cursor[i] = run;
            run += c[j];
        }
    }
    if (blockIdx.x == 0 && t == 0) g_start[n_dst] = E;
}

__global__ __launch_bounds__(256) void permute_kernel(
    const void* __restrict__ src_idx, const void* __restrict__ dst_idx, int E)
{
    int i = blockIdx.x * blockDim.x + threadIdx.x;
    if (i < E) {
        int s = load_idx(src_idx, i);
        int d = load_idx(dst_idx, i);
        int pos = atomicAdd(&g_cursor[d], 1);
        g_perm_src[pos] = s;
    }
}

// ---------------- projection GEMM (FFMA2), column-split for 3 CTAs/SM ----------------
// Each block: 64 rows x 64 cols (half of W). smem = X[128k][66] + Whalf[128k][68] = 68.6KB
// -> 3 CTAs/SM (24 warps) for latency hiding. Per-thread 4x4 tile (2 row-pairs x 4 cols).
#define XT_STRIDE 66
#define WT_STRIDE 68
#define PROJ_SMEM ((128 * XT_STRIDE + 128 * WT_STRIDE) * 4)   // 68608
__global__ __launch_bounds__(256, 3) void proj3_kernel(
    const float* __restrict__ dst_feat, const float* __restrict__ src_feat,
    const float* __restrict__ Wq, const float* __restrict__ bq_,
    const float* __restrict__ Wk, const float* __restrict__ bk_,
    const float* __restrict__ Wv, const float* __restrict__ bv_,
    int n_dst, int n_src, int blocks_q, int blocks_k)
{
    extern __shared__ float sm[];
    float* Xt = sm;                        // [128 k][66]  (X transposed)
    float* Wt = sm + 128 * XT_STRIDE;      // [128 k][68]  (W half, k-major)

    const int tid   = threadIdx.x;
    const int outer = blockIdx.x >> 1;
    const int half  = blockIdx.x & 1;
    const int colbase = half * 64;

    const float *X, *W, *B;
    float* Y = nullptr;
    int N, row0;
    bool v_half = false;
    if (outer < blocks_q) {
        X = dst_feat; W = Wq; B = bq_; Y = g_Q; N = n_dst; row0 = outer * 64;
    } else if (outer < blocks_q + blocks_k) {
        X = src_feat; W = Wk; B = bk_; Y = g_K; N = n_src; row0 = (outer - blocks_q) * 64;
    } else {
        X = src_feat; W = Wv; B = bv_; N = n_src; row0 = (outer - blocks_q - blocks_k) * 64;
        v_half = true;
    }

    // Fill W half: rows colbase..colbase+63 of W, stored k-major. Coalesced LDG.
    const float* Wsl = W + (size_t)colbase * 128;
    #pragma unroll 4
    for (int idx = tid; idx < 64 * 128; idx += 256) {
        int o = idx >> 7, k = idx & 127;
        Wt[k * WT_STRIDE + o] = Wsl[idx];
    }
    // Fill X tile transposed: Xt[k][r]
    #pragma unroll
    for (int idx = tid; idx < 64 * 32; idx += 256) {
        int r = idx >> 5, c4 = idx & 31;
        int row = row0 + r;
        float4 v = (row < N) ? ((const float4*)X)[(size_t)row * 32 + c4]
                             : make_float4(0.f, 0.f, 0.f, 0.f);
        Xt[(c4 * 4 + 0) * XT_STRIDE + r] = v.x;
        Xt[(c4 * 4 + 1) * XT_STRIDE + r] = v.y;
        Xt[(c4 * 4 + 2) * XT_STRIDE + r] = v.z;
        Xt[(c4 * 4 + 3) * XT_STRIDE + r] = v.w;
    }
    __syncthreads();

    const int tcol = tid & 15;     // 4 cols: colbase + tcol*4 .. +3
    const int trow = tid >> 4;     // 4 rows: trow*4 .. +3 (2 packed pairs)

    unsigned long long acc[2][4];  // [row pair][col]
    #pragma unroll
    for (int p = 0; p < 2; p++)
        #pragma unroll
        for (int j = 0; j < 4; j++) acc[p][j] = 0ULL;

    #pragma unroll 4
    for (int k = 0; k < 128; k++) {
        float4 w = *(const float4*)&Wt[k * WT_STRIDE + tcol * 4];
        unsigned long long wp0 = pack2(w.x), wp1 = pack2(w.y),
                           wp2 = pack2(w.z), wp3 = pack2(w.w);
        unsigned long long x0 = *(const unsigned long long*)&Xt[k * XT_STRIDE + trow * 4];
        unsigned long long x1 = *(const unsigned long long*)&Xt[k * XT_STRIDE + trow * 4 + 2];
        fma2(acc[0][0], x0, wp0);
        fma2(acc[0][1], x0, wp1);
        fma2(acc[0][2], x0, wp2);
        fma2(acc[0][3], x0, wp3);
        fma2(acc[1][0], x1, wp0);
        fma2(acc[1][1], x1, wp1);
        fma2(acc[1][2], x1, wp2);
        fma2(acc[1][3], x1, wp3);
    }

    float4 bias = *(const float4*)&B[colbase + tcol * 4];
    #pragma unroll
    for (int p = 0; p < 2; p++) {
        float2 a0 = *(float2*)&acc[p][0];
        float2 a1 = *(float2*)&acc[p][1];
        float2 a2 = *(float2*)&acc[p][2];
        float2 a3 = *(float2*)&acc[p][3];
        int row_e = row0 + trow * 4 + 2 * p;
        float4 oe = make_float4(a0.x + bias.x, a1.x + bias.y, a2.x + bias.z, a3.x + bias.w);
        float4 oo = make_float4(a0.y + bias.x, a1.y + bias.y, a2.y + bias.z, a3.y + bias.w);
        if (v_half) {
            if (row_e < N) {
                __half2 h0 = __floats2half2_rn(oe.x, oe.y);
                __half2 h1 = __floats2half2_rn(oe.z, oe.w);
                uint2 u; u.x = *(uint32_t*)&h0; u.y = *(uint32_t*)&h1;
                ((uint2*)(g_Vh + (size_t)row_e * 128 + colbase))[tcol] = u;
            }
            if (row_e + 1 < N) {
                __half2 h0 = __floats2half2_rn(oo.x, oo.y);
                __half2 h1 = __floats2half2_rn(oo.z, oo.w);
                uint2 u; u.x = *(uint32_t*)&h0; u.y = *(uint32_t*)&h1;
                ((uint2*)(g_Vh + (size_t)(row_e + 1) * 128 + colbase))[tcol] = u;
            }
        } else {
            if (row_e < N)
                ((float4*)Y)[(size_t)row_e * 32 + (colbase >> 2) + tcol] = oe;
            if (row_e + 1 < N)
                ((float4*)Y)[(size_t)(row_e + 1) * 32 + (colbase >> 2) + tcol] = oo;
        }
    }
}

// ---------------- fused attention: one warp per dst, online softmax ----------------
__global__ __launch_bounds__(256) void attn_kernel(float* __restrict__ out, int n_dst)
{
    int w = (blockIdx.x * blockDim.x + threadIdx.x) >> 5;
    if (w >= n_dst) return;
    int lane = threadIdx.x & 31;

    int start = g_start[w];
    int end   = g_start[w + 1];

    float4 q = ((const float4*)(g_Q + (size_t)w * D))[lane];

    float m = -CUDART_INF_F;
    float denom = 0.0f;
    float4 acc = make_float4(0.f, 0.f, 0.f, 0.f);

    for (int p = start; p < end; ++p) {
        int s = __ldg(&g_perm_src[p]);

        float4 k = ((const float4*)(g_K + (size_t)s * D))[lane];
        uint2 vv = ((const uint2*)(g_Vh + (size_t)s * D))[lane];
        float2 v01 = __half22float2(*(__half2*)&vv.x);
        float2 v23 = __half22float2(*(__half2*)&vv.y);

        float dot = q.x * k.x + q.y * k.y + q.z * k.z + q.w * k.w;
        #pragma unroll
        for (int off = 16; off > 0; off >>= 1)
            dot += __shfl_xor_sync(0xFFFFFFFFu, dot, off);

        float sc = dot * INV_SCALE;
        float newm = fmaxf(m, sc);
        float scale = __expf(m - newm);
        float wgt   = __expf(sc - newm);
        denom = denom * scale + wgt;
        acc.x = acc.x * scale + wgt * v01.x;
        acc.y = acc.y * scale + wgt * v01.y;
        acc.z = acc.z * scale + wgt * v23.x;
        acc.w = acc.w * scale + wgt * v23.y;
        m = newm;
    }

    float inv = (denom > 0.0f) ? (1.0f / denom) : 0.0f;
    float4 r = make_float4(acc.x * inv, acc.y * inv, acc.z * inv, acc.w * inv);
    ((float4*)(out + (size_t)w * D))[lane] = r;
}

// ---------------- launch: fork-join two streams (R8 schedule) ----------------
extern "C" void kernel_launch(void* const* d_in, const int* in_sizes, int n_in,
                              void* d_out, int out_size)
{
    const float* src_feat = (const float*)d_in[0];
    const float* dst_feat = (const float*)d_in[1];
    const void*  src_idx  = d_in[2];
    const void*  dst_idx  = d_in[3];
    const float* Wq = (const float*)d_in[4];
    const float* bq = (const float*)d_in[5];
    const float* Wk = (const float*)d_in[6];
    const float* bk = (const float*)d_in[7];
    const float* Wv = (const float*)d_in[8];
    const float* bv = (const float*)d_in[9];
    float* out = (float*)d_out;

    int n_src = in_sizes[0] / D;
    int n_dst = in_sizes[1] / D;
    int E     = in_sizes[2];

    static cudaStream_t s2 = nullptr;
    static cudaEvent_t evFork = nullptr, evJoin = nullptr;
    static int attr_set = 0;
    if (!attr_set) {
        cudaFuncSetAttribute(proj3_kernel, cudaFuncAttributeMaxDynamicSharedMemorySize, PROJ_SMEM);
        cudaStreamCreateWithFlags(&s2, cudaStreamNonBlocking);
        cudaEventCreateWithFlags(&evFork, cudaEventDisableTiming);
        cudaEventCreateWithFlags(&evJoin, cudaEventDisableTiming);
        attr_set = 1;
    }

    // Fork: stream B handles the index/sort chain.
    cudaEventRecord(evFork, 0);
    cudaStreamWaitEvent(s2, evFork, 0);

    detect_idx_kernel<<<1, 64, 0, s2>>>(src_idx, dst_idx, n_src, n_dst, E);
    zero_counts_kernel<<<(n_dst + 255) / 256, 256, 0, s2>>>(n_dst);
    hist_kernel<<<(E + 255) / 256, 256, 0, s2>>>(dst_idx, E);
    int scan_blocks = (n_dst + 1023) / 1024;
    scan_bsum_kernel<<<scan_blocks, 256, 0, s2>>>(n_dst);
    scan_top_kernel<<<1, 128, 0, s2>>>(scan_blocks);
    scan_apply_kernel<<<scan_blocks, 256, 0, s2>>>(n_dst, E);
    permute_kernel<<<(E + 255) / 256, 256, 0, s2>>>(src_idx, dst_idx, E);
    cudaEventRecord(evJoin, s2);

    // Stream A: merged projections, column-split (Q, K fp32; V fp16).
    int blocks_q = (n_dst + 63) / 64;
    int blocks_k = (n_src + 63) / 64;
    int blocks_v = (n_src + 63) / 64;
    proj3_kernel<<<2 * (blocks_q + blocks_k + blocks_v), 256, PROJ_SMEM>>>(
        dst_feat, src_feat, Wq, bq, Wk, bk, Wv, bv, n_dst, n_src, blocks_q, blocks_k);

    // Join: attention needs Q/K/V and the sorted edge lists.
    cudaStreamWaitEvent(0, evJoin, 0);
    attn_kernel<<<(n_dst + 7) / 8, 256>>>(out, n_dst);
}

// round 13
// speedup vs baseline: 1.1061x; 1.1061x over previous
#include <cuda_runtime.h>
#include <cuda_fp16.h>
#include <math_constants.h>
#include <cstdint>

// Problem constants (match reference)
#define D         128
#define N_SRC_MAX 50000
#define N_DST_MAX 50000
#define E_MAX     1600000
#define INV_SCALE 0.25f          // 1/sqrt(128/8) = 1/4

// ---------------- scratch (no allocations allowed) ----------------
__device__ __align__(128) float  g_Q[N_DST_MAX * D];
__device__ __align__(128) __half g_Kh[N_SRC_MAX * D];
__device__ __align__(128) __half g_Vh[N_SRC_MAX * D];
__device__ __align__(128) int    g_count[N_DST_MAX];
__device__ __align__(128) int    g_start[N_DST_MAX + 1];
__device__ __align__(128) int    g_cursor[N_DST_MAX];
__device__ __align__(128) int    g_perm_src[E_MAX];
__device__ __align__(128) int    g_bsum[128];
__device__ int g_is64;

// ---------------- helpers ----------------
__device__ __forceinline__ int load_idx(const void* p, int i) {
    if (g_is64) return (int)((const long long*)p)[i];
    return ((const int*)p)[i];
}
__device__ __forceinline__ void fma2(unsigned long long& d,
                                     unsigned long long a, unsigned long long b) {
    asm("fma.rn.f32x2 %0, %1, %2, %0;" : "+l"(d) : "l"(a), "l"(b));
}
__device__ __forceinline__ unsigned long long pack2(float x) {
    unsigned long long r;
    asm("mov.b64 %0, {%1, %1};" : "=l"(r) : "f"(x));
    return r;
}

// ---------------- dtype detection ----------------
__global__ void detect_idx_kernel(const void* src_idx, const void* dst_idx,
                                  int n_src, int n_dst, int E) {
    if (threadIdx.x == 0) g_is64 = 1;
    __syncthreads();
    int i = threadIdx.x;
    int limit = (E / 2 < 64) ? E / 2 : 64;
    if (i < limit) {
        long long s = ((const long long*)src_idx)[i];
        long long d = ((const long long*)dst_idx)[i];
        bool ok = (s >= 0 && s < n_src && d >= 0 && d < n_dst);
        if (!ok) atomicExch(&g_is64, 0);
    }
}

__global__ void zero_counts_kernel(int n_dst) {
    int i = blockIdx.x * blockDim.x + threadIdx.x;
    if (i < n_dst) g_count[i] = 0;
}

__global__ __launch_bounds__(256) void hist_kernel(const void* __restrict__ dst_idx, int E) {
    int i = blockIdx.x * blockDim.x + threadIdx.x;
    if (i < E) atomicAdd(&g_count[load_idx(dst_idx, i)], 1);
}

// ---------------- parallel exclusive scan (3 kernels) ----------------
__global__ __launch_bounds__(256) void scan_bsum_kernel(int n_dst) {
    int t = threadIdx.x;
    int base = blockIdx.x * 1024 + t * 4;
    int v = 0;
    #pragma unroll
    for (int j = 0; j < 4; j++) {
        int i = base + j;
        if (i < n_dst) v += g_count[i];
    }
    #pragma unroll
    for (int off = 16; off; off >>= 1) v += __shfl_xor_sync(0xFFFFFFFFu, v, off);
    __shared__ int ws[8];
    if ((t & 31) == 0) ws[t >> 5] = v;
    __syncthreads();
    if (t < 8) {
        int u = ws[t];
        #pragma unroll
        for (int off = 4; off; off >>= 1) u += __shfl_xor_sync(0xFFu, u, off);
        if (t == 0) g_bsum[blockIdx.x] = u;
    }
}

__global__ __launch_bounds__(128) void scan_top_kernel(int nblocks) {
    __shared__ int s[128];
    int t = threadIdx.x;
    s[t] = (t < nblocks) ? g_bsum[t] : 0;
    __syncthreads();
    for (int off = 1; off < 128; off <<= 1) {
        int v = (t >= off) ? s[t - off] : 0;
        __syncthreads();
        s[t] += v;
        __syncthreads();
    }
    int excl = (t == 0) ? 0 : s[t - 1];
    if (t < nblocks) g_bsum[t] = excl;
}

__global__ __launch_bounds__(256) void scan_apply_kernel(int n_dst, int E) {
    __shared__ int ws[8];
    int t = threadIdx.x;
    int lane = t & 31, wid = t >> 5;
    int base = blockIdx.x * 1024 + t * 4;
    int c[4];
    int s_local = 0;
    #pragma unroll
    for (int j = 0; j < 4; j++) {
        int i = base + j;
        c[j] = (i < n_dst) ? g_count[i] : 0;
        s_local += c[j];
    }
    int v = s_local;
    #pragma unroll
    for (int off = 1; off < 32; off <<= 1) {
        int u = __shfl_up_sync(0xFFFFFFFFu, v, off);
        if (lane >= off) v += u;
    }
    if (lane == 31) ws[wid] = v;
    __syncthreads();
    if (t < 8) {
        int u = ws[t];
        #pragma unroll
        for (int off = 1; off < 8; off <<= 1) {
            int x = __shfl_up_sync(0xFFu, u, off);
            if (t >= off) u += x;
        }
        ws[t] = u;
    }
    __syncthreads();
    int run = v - s_local + (wid ? ws[wid - 1] : 0) + g_bsum[blockIdx.x];
    #pragma unroll
    for (int j = 0; j < 4; j++) {
        int i = base + j;
        if (i < n_dst) {
            g_start[i]  = run;
            g_cursor[i] = run;
            run += c[j];
        }
    }
    if (blockIdx.x == 0 && t == 0) g_start[n_dst] = E;
}

__global__ __launch_bounds__(256) void permute_kernel(
    const void* __restrict__ src_idx, const void* __restrict__ dst_idx, int E)
{
    int i = blockIdx.x * blockDim.x + threadIdx.x;
    if (i < E) {
        int s = load_idx(src_idx, i);
        int d = load_idx(dst_idx, i);
        int pos = atomicAdd(&g_cursor[d], 1);
        g_perm_src[pos] = s;
    }
}

// ---------------- merged projection GEMM (FFMA2), all 3 matrices in one launch ----------------
// mode per block: Q -> fp32, K -> fp16, V -> fp16
#define XT_STRIDE 66
#define WT_STRIDE 132
#define PROJ_SMEM ((128 * XT_STRIDE + 128 * WT_STRIDE) * 4)
__global__ __launch_bounds__(256) void proj3_kernel(
    const float* __restrict__ dst_feat, const float* __restrict__ src_feat,
    const float* __restrict__ Wq, const float* __restrict__ bq_,
    const float* __restrict__ Wk, const float* __restrict__ bk_,
    const float* __restrict__ Wv, const float* __restrict__ bv_,
    int n_dst, int n_src, int blocks_q, int blocks_k)
{
    extern __shared__ float sm[];
    float* Xt = sm;                        // [128 k][66]
    float* Wt = sm + 128 * XT_STRIDE;      // [128 k][132]

    const int tid = threadIdx.x;
    const int bid = blockIdx.x;

    const float *X, *W, *B;
    int N, row0;
    int mode;                              // 0=Q(fp32), 1=K(fp16), 2=V(fp16)
    if (bid < blocks_q) {
        X = dst_feat; W = Wq; B = bq_; N = n_dst; row0 = bid * 64; mode = 0;
    } else if (bid < blocks_q + blocks_k) {
        X = src_feat; W = Wk; B = bk_; N = n_src; row0 = (bid - blocks_q) * 64; mode = 1;
    } else {
        X = src_feat; W = Wv; B = bv_; N = n_src; row0 = (bid - blocks_q - blocks_k) * 64; mode = 2;
    }

    #pragma unroll 4
    for (int idx = tid; idx < 128 * 128; idx += 256) {
        int o = idx >> 7, k = idx & 127;
        Wt[k * WT_STRIDE + o] = W[idx];
    }
    #pragma unroll
    for (int idx = tid; idx < 64 * 32; idx += 256) {
        int r = idx >> 5, c4 = idx & 31;
        int row = row0 + r;
        float4 v = (row < N) ? ((const float4*)X)[(size_t)row * 32 + c4]
                             : make_float4(0.f, 0.f, 0.f, 0.f);
        Xt[(c4 * 4 + 0) * XT_STRIDE + r] = v.x;
        Xt[(c4 * 4 + 1) * XT_STRIDE + r] = v.y;
        Xt[(c4 * 4 + 2) * XT_STRIDE + r] = v.z;
        Xt[(c4 * 4 + 3) * XT_STRIDE + r] = v.w;
    }
    __syncthreads();

    const int tcol = tid & 31;    // output cols tcol*4 .. tcol*4+3
    const int trow = tid >> 5;    // rows trow*8 .. trow*8+7 (4 packed pairs)

    unsigned long long acc[4][4]; // [row pair p][col j]
    #pragma unroll
    for (int p = 0; p < 4; p++)
        #pragma unroll
        for (int j = 0; j < 4; j++) acc[p][j] = 0ULL;

    #pragma unroll 4
    for (int k = 0; k < 128; k++) {
        float4 w = *(const float4*)&Wt[k * WT_STRIDE + tcol * 4];
        unsigned long long wp0 = pack2(w.x), wp1 = pack2(w.y),
                           wp2 = pack2(w.z), wp3 = pack2(w.w);
        const unsigned long long* xrow =
            (const unsigned long long*)&Xt[k * XT_STRIDE + trow * 8];
        #pragma unroll
        for (int p = 0; p < 4; p++) {
            unsigned long long xp = xrow[p];
            fma2(acc[p][0], xp, wp0);
            fma2(acc[p][1], xp, wp1);
            fma2(acc[p][2], xp, wp2);
            fma2(acc[p][3], xp, wp3);
        }
    }

    float4 bias = *(const float4*)&B[tcol * 4];
    __half* Hout = (mode == 1) ? g_Kh : g_Vh;
    #pragma unroll
    for (int p = 0; p < 4; p++) {
        float2 a0 = *(float2*)&acc[p][0];
        float2 a1 = *(float2*)&acc[p][1];
        float2 a2 = *(float2*)&acc[p][2];
        float2 a3 = *(float2*)&acc[p][3];
        int row_e = row0 + trow * 8 + 2 * p;
        float4 oe = make_float4(a0.x + bias.x, a1.x + bias.y, a2.x + bias.z, a3.x + bias.w);
        float4 oo = make_float4(a0.y + bias.x, a1.y + bias.y, a2.y + bias.z, a3.y + bias.w);
        if (mode != 0) {
            if (row_e < N) {
                __half2 h0 = __floats2half2_rn(oe.x, oe.y);
                __half2 h1 = __floats2half2_rn(oe.z, oe.w);
                uint2 u; u.x = *(uint32_t*)&h0; u.y = *(uint32_t*)&h1;
                ((uint2*)(Hout + (size_t)row_e * 128))[tcol] = u;
            }
            if (row_e + 1 < N) {
                __half2 h0 = __floats2half2_rn(oo.x, oo.y);
                __half2 h1 = __floats2half2_rn(oo.z, oo.w);
                uint2 u; u.x = *(uint32_t*)&h0; u.y = *(uint32_t*)&h1;
                ((uint2*)(Hout + (size_t)(row_e + 1) * 128))[tcol] = u;
            }
        } else {
            if (row_e < N)     ((float4*)g_Q)[(size_t)row_e * 32 + tcol] = oe;
            if (row_e + 1 < N) ((float4*)g_Q)[(size_t)(row_e + 1) * 32 + tcol] = oo;
        }
    }
}

// ---------------- fused attention: one warp per dst, online softmax ----------------
__global__ __launch_bounds__(256) void attn_kernel(float* __restrict__ out, int n_dst)
{
    int w = (blockIdx.x * blockDim.x + threadIdx.x) >> 5;
    if (w >= n_dst) return;
    int lane = threadIdx.x & 31;

    int start = g_start[w];
    int end   = g_start[w + 1];

    float4 q = ((const float4*)(g_Q + (size_t)w * D))[lane];
    // fold 1/sqrt(d_head) into q (exact: power of two)
    q.x *= INV_SCALE; q.y *= INV_SCALE; q.z *= INV_SCALE; q.w *= INV_SCALE;

    float m = -CUDART_INF_F;
    float denom = 0.0f;
    float4 acc = make_float4(0.f, 0.f, 0.f, 0.f);

    for (int p = start; p < end; ++p) {
        int s = __ldg(&g_perm_src[p]);

        uint2 kk = ((const uint2*)(g_Kh + (size_t)s * D))[lane];
        uint2 vv = ((const uint2*)(g_Vh + (size_t)s * D))[lane];
        float2 k01 = __half22float2(*(__half2*)&kk.x);
        float2 k23 = __half22float2(*(__half2*)&kk.y);
        float2 v01 = __half22float2(*(__half2*)&vv.x);
        float2 v23 = __half22float2(*(__half2*)&vv.y);

        float dot = q.x * k01.x + q.y * k01.y + q.z * k23.x + q.w * k23.y;
        #pragma unroll
        for (int off = 16; off > 0; off >>= 1)
            dot += __shfl_xor_sync(0xFFFFFFFFu, dot, off);

        float sc = dot;
        float newm = fmaxf(m, sc);
        float scale = __expf(m - newm);
        float wgt   = __expf(sc - newm);
        denom = denom * scale + wgt;
        acc.x = acc.x * scale + wgt * v01.x;
        acc.y = acc.y * scale + wgt * v01.y;
        acc.z = acc.z * scale + wgt * v23.x;
        acc.w = acc.w * scale + wgt * v23.y;
        m = newm;
    }

    float inv = (denom > 0.0f) ? (1.0f / denom) : 0.0f;
    float4 r = make_float4(acc.x * inv, acc.y * inv, acc.z * inv, acc.w * inv);
    ((float4*)(out + (size_t)w * D))[lane] = r;
}

// ---------------- launch: fork-join two streams (R8 schedule) ----------------
extern "C" void kernel_launch(void* const* d_in, const int* in_sizes, int n_in,
                              void* d_out, int out_size)
{
    const float* src_feat = (const float*)d_in[0];
    const float* dst_feat = (const float*)d_in[1];
    const void*  src_idx  = d_in[2];
    const void*  dst_idx  = d_in[3];
    const float* Wq = (const float*)d_in[4];
    const float* bq = (const float*)d_in[5];
    const float* Wk = (const float*)d_in[6];
    const float* bk = (const float*)d_in[7];
    const float* Wv = (const float*)d_in[8];
    const float* bv = (const float*)d_in[9];
    float* out = (float*)d_out;

    int n_src = in_sizes[0] / D;
    int n_dst = in_sizes[1] / D;
    int E     = in_sizes[2];

    static cudaStream_t s2 = nullptr;
    static cudaEvent_t evFork = nullptr, evJoin = nullptr;
    static int attr_set = 0;
    if (!attr_set) {
        cudaFuncSetAttribute(proj3_kernel, cudaFuncAttributeMaxDynamicSharedMemorySize, PROJ_SMEM);
        cudaStreamCreateWithFlags(&s2, cudaStreamNonBlocking);
        cudaEventCreateWithFlags(&evFork, cudaEventDisableTiming);
        cudaEventCreateWithFlags(&evJoin, cudaEventDisableTiming);
        attr_set = 1;
    }

    // Fork: stream B handles the index/sort chain.
    cudaEventRecord(evFork, 0);
    cudaStreamWaitEvent(s2, evFork, 0);

    detect_idx_kernel<<<1, 64, 0, s2>>>(src_idx, dst_idx, n_src, n_dst, E);
    zero_counts_kernel<<<(n_dst + 255) / 256, 256, 0, s2>>>(n_dst);
    hist_kernel<<<(E + 255) / 256, 256, 0, s2>>>(dst_idx, E);
    int scan_blocks = (n_dst + 1023) / 1024;
    scan_bsum_kernel<<<scan_blocks, 256, 0, s2>>>(n_dst);
    scan_top_kernel<<<1, 128, 0, s2>>>(scan_blocks);
    scan_apply_kernel<<<scan_blocks, 256, 0, s2>>>(n_dst, E);
    permute_kernel<<<(E + 255) / 256, 256, 0, s2>>>(src_idx, dst_idx, E);
    cudaEventRecord(evJoin, s2);

    // Stream A: merged projections (Q fp32; K, V fp16).
    int blocks_q = (n_dst + 63) / 64;
    int blocks_k = (n_src + 63) / 64;
    int blocks_v = (n_src + 63) / 64;
    proj3_kernel<<<blocks_q + blocks_k + blocks_v, 256, PROJ_SMEM>>>(
        dst_feat, src_feat, Wq, bq, Wk, bk, Wv, bv, n_dst, n_src, blocks_q, blocks_k);

    // Join: attention needs Q/K/V and the sorted edge lists.
    cudaStreamWaitEvent(0, evJoin, 0);
    attn_kernel<<<(n_dst + 7) / 8, 256>>>(out, n_dst);
}

// round 14
// speedup vs baseline: 1.1999x; 1.0848x over previous
#include <cuda_runtime.h>
#include <cuda_fp16.h>
#include <math_constants.h>
#include <cstdint>

// Problem constants (match reference)
#define D         128
#define N_SRC_MAX 50000
#define N_DST_MAX 50000
#define E_MAX     1600000
#define INV_SCALE 0.25f          // 1/sqrt(128/8) = 1/4

// ---------------- scratch (no allocations allowed) ----------------
__device__ __align__(128) float  g_Q[N_DST_MAX * D];
__device__ __align__(128) float  g_K[N_SRC_MAX * D];
__device__ __align__(128) __half g_Vh[N_SRC_MAX * D];
__device__ __align__(128) int    g_count[N_DST_MAX];
__device__ __align__(128) int    g_start[N_DST_MAX + 1];
__device__ __align__(128) int    g_cursor[N_DST_MAX];
__device__ __align__(128) int    g_perm_src[E_MAX];
__device__ __align__(128) int    g_bsum[128];
__device__ int g_is64;

// ---------------- helpers ----------------
__device__ __forceinline__ int load_idx(const void* p, int i) {
    if (g_is64) return (int)((const long long*)p)[i];
    return ((const int*)p)[i];
}
__device__ __forceinline__ void fma2(unsigned long long& d,
                                     unsigned long long a, unsigned long long b) {
    asm("fma.rn.f32x2 %0, %1, %2, %0;" : "+l"(d) : "l"(a), "l"(b));
}
__device__ __forceinline__ unsigned long long pack2(float x) {
    unsigned long long r;
    asm("mov.b64 %0, {%1, %1};" : "=l"(r) : "f"(x));
    return r;
}

// ---------------- dtype detection ----------------
__global__ void detect_idx_kernel(const void* src_idx, const void* dst_idx,
                                  int n_src, int n_dst, int E) {
    if (threadIdx.x == 0) g_is64 = 1;
    __syncthreads();
    int i = threadIdx.x;
    int limit = (E / 2 < 64) ? E / 2 : 64;
    if (i < limit) {
        long long s = ((const long long*)src_idx)[i];
        long long d = ((const long long*)dst_idx)[i];
        bool ok = (s >= 0 && s < n_src && d >= 0 && d < n_dst);
        if (!ok) atomicExch(&g_is64, 0);
    }
}

__global__ void zero_counts_kernel(int n_dst) {
    int i = blockIdx.x * blockDim.x + threadIdx.x;
    if (i < n_dst) g_count[i] = 0;
}

__global__ __launch_bounds__(256) void hist_kernel(const void* __restrict__ dst_idx, int E) {
    int i = blockIdx.x * blockDim.x + threadIdx.x;
    if (i < E) atomicAdd(&g_count[load_idx(dst_idx, i)], 1);
}

// ---------------- parallel exclusive scan (3 kernels) ----------------
__global__ __launch_bounds__(256) void scan_bsum_kernel(int n_dst) {
    int t = threadIdx.x;
    int base = blockIdx.x * 1024 + t * 4;
    int v = 0;
    #pragma unroll
    for (int j = 0; j < 4; j++) {
        int i = base + j;
        if (i < n_dst) v += g_count[i];
    }
    #pragma unroll
    for (int off = 16; off; off >>= 1) v += __shfl_xor_sync(0xFFFFFFFFu, v, off);
    __shared__ int ws[8];
    if ((t & 31) == 0) ws[t >> 5] = v;
    __syncthreads();
    if (t < 8) {
        int u = ws[t];
        #pragma unroll
        for (int off = 4; off; off >>= 1) u += __shfl_xor_sync(0xFFu, u, off);
        if (t == 0) g_bsum[blockIdx.x] = u;
    }
}

__global__ __launch_bounds__(128) void scan_top_kernel(int nblocks) {
    __shared__ int s[128];
    int t = threadIdx.x;
    s[t] = (t < nblocks) ? g_bsum[t] : 0;
    __syncthreads();
    for (int off = 1; off < 128; off <<= 1) {
        int v = (t >= off) ? s[t - off] : 0;
        __syncthreads();
        s[t] += v;
        __syncthreads();
    }
    int excl = (t == 0) ? 0 : s[t - 1];
    if (t < nblocks) g_bsum[t] = excl;
}

__global__ __launch_bounds__(256) void scan_apply_kernel(int n_dst, int E) {
    __shared__ int ws[8];
    int t = threadIdx.x;
    int lane = t & 31, wid = t >> 5;
    int base = blockIdx.x * 1024 + t * 4;
    int c[4];
    int s_local = 0;
    #pragma unroll
    for (int j = 0; j < 4; j++) {
        int i = base + j;
        c[j] = (i < n_dst) ? g_count[i] : 0;
        s_local += c[j];
    }
    int v = s_local;
    #pragma unroll
    for (int off = 1; off < 32; off <<= 1) {
        int u = __shfl_up_sync(0xFFFFFFFFu, v, off);
        if (lane >= off) v += u;
    }
    if (lane == 31) ws[wid] = v;
    __syncthreads();
    if (t < 8) {
        int u = ws[t];
        #pragma unroll
        for (int off = 1; off < 8; off <<= 1) {
            int x = __shfl_up_sync(0xFFu, u, off);
            if (t >= off) u += x;
        }
        ws[t] = u;
    }
    __syncthreads();
    int run = v - s_local + (wid ? ws[wid - 1] : 0) + g_bsum[blockIdx.x];
    #pragma unroll
    for (int j = 0; j < 4; j++) {
        int i = base + j;
        if (i < n_dst) {
            g_start[i]  = run;
            g_cursor[i] = run;
            run += c[j];
        }
    }
    if (blockIdx.x == 0 && t == 0) g_start[n_dst] = E;
}

__global__ __launch_bounds__(256) void permute_kernel(
    const void* __restrict__ src_idx, const void* __restrict__ dst_idx, int E)
{
    int i = blockIdx.x * blockDim.x + threadIdx.x;
    if (i < E) {
        int s = load_idx(src_idx, i);
        int d = load_idx(dst_idx, i);
        int pos = atomicAdd(&g_cursor[d], 1);
        g_perm_src[pos] = s;
    }
}

// ---------------- merged projection GEMM (FFMA2), all 3 matrices in one launch ----------------
#define XT_STRIDE 66
#define WT_STRIDE 132
#define PROJ_SMEM ((128 * XT_STRIDE + 128 * WT_STRIDE) * 4)
__global__ __launch_bounds__(256) void proj3_kernel(
    const float* __restrict__ dst_feat, const float* __restrict__ src_feat,
    const float* __restrict__ Wq, const float* __restrict__ bq_,
    const float* __restrict__ Wk, const float* __restrict__ bk_,
    const float* __restrict__ Wv, const float* __restrict__ bv_,
    int n_dst, int n_src, int blocks_q, int blocks_k)
{
    extern __shared__ float sm[];
    float* Xt = sm;                        // [128 k][66]
    float* Wt = sm + 128 * XT_STRIDE;      // [128 k][132]

    const int tid = threadIdx.x;
    const int bid = blockIdx.x;

    const float *X, *W, *B;
    float* Y = nullptr;
    int N, row0;
    bool v_half = false;
    if (bid < blocks_q) {
        X = dst_feat; W = Wq; B = bq_; Y = g_Q; N = n_dst; row0 = bid * 64;
    } else if (bid < blocks_q + blocks_k) {
        X = src_feat; W = Wk; B = bk_; Y = g_K; N = n_src; row0 = (bid - blocks_q) * 64;
    } else {
        X = src_feat; W = Wv; B = bv_; N = n_src; row0 = (bid - blocks_q - blocks_k) * 64;
        v_half = true;
    }

    #pragma unroll 4
    for (int idx = tid; idx < 128 * 128; idx += 256) {
        int o = idx >> 7, k = idx & 127;
        Wt[k * WT_STRIDE + o] = W[idx];
    }
    #pragma unroll
    for (int idx = tid; idx < 64 * 32; idx += 256) {
        int r = idx >> 5, c4 = idx & 31;
        int row = row0 + r;
        float4 v = (row < N) ? ((const float4*)X)[(size_t)row * 32 + c4]
                             : make_float4(0.f, 0.f, 0.f, 0.f);
        Xt[(c4 * 4 + 0) * XT_STRIDE + r] = v.x;
        Xt[(c4 * 4 + 1) * XT_STRIDE + r] = v.y;
        Xt[(c4 * 4 + 2) * XT_STRIDE + r] = v.z;
        Xt[(c4 * 4 + 3) * XT_STRIDE + r] = v.w;
    }
    __syncthreads();

    const int tcol = tid & 31;
    const int trow = tid >> 5;

    unsigned long long acc[4][4];
    #pragma unroll
    for (int p = 0; p < 4; p++)
        #pragma unroll
        for (int j = 0; j < 4; j++) acc[p][j] = 0ULL;

    #pragma unroll 4
    for (int k = 0; k < 128; k++) {
        float4 w = *(const float4*)&Wt[k * WT_STRIDE + tcol * 4];
        unsigned long long wp0 = pack2(w.x), wp1 = pack2(w.y),
                           wp2 = pack2(w.z), wp3 = pack2(w.w);
        const unsigned long long* xrow =
            (const unsigned long long*)&Xt[k * XT_STRIDE + trow * 8];
        #pragma unroll
        for (int p = 0; p < 4; p++) {
            unsigned long long xp = xrow[p];
            fma2(acc[p][0], xp, wp0);
            fma2(acc[p][1], xp, wp1);
            fma2(acc[p][2], xp, wp2);
            fma2(acc[p][3], xp, wp3);
        }
    }

    float4 bias = *(const float4*)&B[tcol * 4];
    #pragma unroll
    for (int p = 0; p < 4; p++) {
        float2 a0 = *(float2*)&acc[p][0];
        float2 a1 = *(float2*)&acc[p][1];
        float2 a2 = *(float2*)&acc[p][2];
        float2 a3 = *(float2*)&acc[p][3];
        int row_e = row0 + trow * 8 + 2 * p;
        float4 oe = make_float4(a0.x + bias.x, a1.x + bias.y, a2.x + bias.z, a3.x + bias.w);
        float4 oo = make_float4(a0.y + bias.x, a1.y + bias.y, a2.y + bias.z, a3.y + bias.w);
        if (v_half) {
            if (row_e < N) {
                __half2 h0 = __floats2half2_rn(oe.x, oe.y);
                __half2 h1 = __floats2half2_rn(oe.z, oe.w);
                uint2 u; u.x = *(uint32_t*)&h0; u.y = *(uint32_t*)&h1;
                ((uint2*)(g_Vh + (size_t)row_e * 128))[tcol] = u;
            }
            if (row_e + 1 < N) {
                __half2 h0 = __floats2half2_rn(oo.x, oo.y);
                __half2 h1 = __floats2half2_rn(oo.z, oo.w);
                uint2 u; u.x = *(uint32_t*)&h0; u.y = *(uint32_t*)&h1;
                ((uint2*)(g_Vh + (size_t)(row_e + 1) * 128))[tcol] = u;
            }
        } else {
            if (row_e < N)     ((float4*)Y)[(size_t)row_e * 32 + tcol] = oe;
            if (row_e + 1 < N) ((float4*)Y)[(size_t)(row_e + 1) * 32 + tcol] = oo;
        }
    }
}

// ---------------- fused attention: one warp per dst, 4-edge-unrolled online softmax ----------------
__global__ __launch_bounds__(256) void attn_kernel(float* __restrict__ out, int n_dst)
{
    int w = (blockIdx.x * blockDim.x + threadIdx.x) >> 5;
    if (w >= n_dst) return;
    int lane = threadIdx.x & 31;

    int start = g_start[w];
    int end   = g_start[w + 1];

    float4 q = ((const float4*)(g_Q + (size_t)w * D))[lane];
    q.x *= INV_SCALE; q.y *= INV_SCALE; q.z *= INV_SCALE; q.w *= INV_SCALE;

    float m = -CUDART_INF_F;
    float denom = 0.0f;
    float4 acc = make_float4(0.f, 0.f, 0.f, 0.f);

    int p = start;
    // main loop: 4 edges per iteration; interleaved shfl chains + group softmax
    for (; p + 4 <= end; p += 4) {
        int s0 = __ldg(&g_perm_src[p + 0]);
        int s1 = __ldg(&g_perm_src[p + 1]);
        int s2 = __ldg(&g_perm_src[p + 2]);
        int s3 = __ldg(&g_perm_src[p + 3]);

        float4 k0 = ((const float4*)(g_K + (size_t)s0 * D))[lane];
        float4 k1 = ((const float4*)(g_K + (size_t)s1 * D))[lane];
        float4 k2 = ((const float4*)(g_K + (size_t)s2 * D))[lane];
        float4 k3 = ((const float4*)(g_K + (size_t)s3 * D))[lane];
        uint2 u0 = ((const uint2*)(g_Vh + (size_t)s0 * D))[lane];
        uint2 u1 = ((const uint2*)(g_Vh + (size_t)s1 * D))[lane];
        uint2 u2 = ((const uint2*)(g_Vh + (size_t)s2 * D))[lane];
        uint2 u3 = ((const uint2*)(g_Vh + (size_t)s3 * D))[lane];

        float d0 = q.x * k0.x + q.y * k0.y + q.z * k0.z + q.w * k0.w;
        float d1 = q.x * k1.x + q.y * k1.y + q.z * k1.z + q.w * k1.w;
        float d2 = q.x * k2.x + q.y * k2.y + q.z * k2.z + q.w * k2.w;
        float d3 = q.x * k3.x + q.y * k3.y + q.z * k3.z + q.w * k3.w;

        #pragma unroll
        for (int off = 16; off > 0; off >>= 1) {
            d0 += __shfl_xor_sync(0xFFFFFFFFu, d0, off);
            d1 += __shfl_xor_sync(0xFFFFFFFFu, d1, off);
            d2 += __shfl_xor_sync(0xFFFFFFFFu, d2, off);
            d3 += __shfl_xor_sync(0xFFFFFFFFu, d3, off);
        }

        float m_new = fmaxf(m, fmaxf(fmaxf(d0, d1), fmaxf(d2, d3)));
        float scale = __expf(m - m_new);
        float w0 = __expf(d0 - m_new);
        float w1 = __expf(d1 - m_new);
        float w2 = __expf(d2 - m_new);
        float w3 = __expf(d3 - m_new);

        float2 v0a = __half22float2(*(__half2*)&u0.x), v0b = __half22float2(*(__half2*)&u0.y);
        float2 v1a = __half22float2(*(__half2*)&u1.x), v1b = __half22float2(*(__half2*)&u1.y);
        float2 v2a = __half22float2(*(__half2*)&u2.x), v2b = __half22float2(*(__half2*)&u2.y);
        float2 v3a = __half22float2(*(__half2*)&u3.x), v3b = __half22float2(*(__half2*)&u3.y);

        denom = denom * scale + ((w0 + w1) + (w2 + w3));
        acc.x = acc.x * scale + ((w0 * v0a.x + w1 * v1a.x) + (w2 * v2a.x + w3 * v3a.x));
        acc.y = acc.y * scale + ((w0 * v0a.y + w1 * v1a.y) + (w2 * v2a.y + w3 * v3a.y));
        acc.z = acc.z * scale + ((w0 * v0b.x + w1 * v1b.x) + (w2 * v2b.x + w3 * v3b.x));
        acc.w = acc.w * scale + ((w0 * v0b.y + w1 * v1b.y) + (w2 * v2b.y + w3 * v3b.y));
        m = m_new;
    }
    // tail
    for (; p < end; ++p) {
        int s = __ldg(&g_perm_src[p]);
        float4 k = ((const float4*)(g_K + (size_t)s * D))[lane];
        uint2 vv = ((const uint2*)(g_Vh + (size_t)s * D))[lane];
        float2 v01 = __half22float2(*(__half2*)&vv.x);
        float2 v23 = __half22float2(*(__half2*)&vv.y);

        float dot = q.x * k.x + q.y * k.y + q.z * k.z + q.w * k.w;
        #pragma unroll
        for (int off = 16; off > 0; off >>= 1)
            dot += __shfl_xor_sync(0xFFFFFFFFu, dot, off);

        float m_new = fmaxf(m, dot);
        float scale = __expf(m - m_new);
        float wgt   = __expf(dot - m_new);
        denom = denom * scale + wgt;
        acc.x = acc.x * scale + wgt * v01.x;
        acc.y = acc.y * scale + wgt * v01.y;
        acc.z = acc.z * scale + wgt * v23.x;
        acc.w = acc.w * scale + wgt * v23.y;
        m = m_new;
    }

    float inv = (denom > 0.0f) ? (1.0f / denom) : 0.0f;
    float4 r = make_float4(acc.x * inv, acc.y * inv, acc.z * inv, acc.w * inv);
    ((float4*)(out + (size_t)w * D))[lane] = r;
}

// ---------------- launch: fork-join two streams (R8 schedule) ----------------
extern "C" void kernel_launch(void* const* d_in, const int* in_sizes, int n_in,
                              void* d_out, int out_size)
{
    const float* src_feat = (const float*)d_in[0];
    const float* dst_feat = (const float*)d_in[1];
    const void*  src_idx  = d_in[2];
    const void*  dst_idx  = d_in[3];
    const float* Wq = (const float*)d_in[4];
    const float* bq = (const float*)d_in[5];
    const float* Wk = (const float*)d_in[6];
    const float* bk = (const float*)d_in[7];
    const float* Wv = (const float*)d_in[8];
    const float* bv = (const float*)d_in[9];
    float* out = (float*)d_out;

    int n_src = in_sizes[0] / D;
    int n_dst = in_sizes[1] / D;
    int E     = in_sizes[2];

    static cudaStream_t s2 = nullptr;
    static cudaEvent_t evFork = nullptr, evJoin = nullptr;
    static int attr_set = 0;
    if (!attr_set) {
        cudaFuncSetAttribute(proj3_kernel, cudaFuncAttributeMaxDynamicSharedMemorySize, PROJ_SMEM);
        cudaStreamCreateWithFlags(&s2, cudaStreamNonBlocking);
        cudaEventCreateWithFlags(&evFork, cudaEventDisableTiming);
        cudaEventCreateWithFlags(&evJoin, cudaEventDisableTiming);
        attr_set = 1;
    }

    // Fork: stream B handles the index/sort chain.
    cudaEventRecord(evFork, 0);
    cudaStreamWaitEvent(s2, evFork, 0);

    detect_idx_kernel<<<1, 64, 0, s2>>>(src_idx, dst_idx, n_src, n_dst, E);
    zero_counts_kernel<<<(n_dst + 255) / 256, 256, 0, s2>>>(n_dst);
    hist_kernel<<<(E + 255) / 256, 256, 0, s2>>>(dst_idx, E);
    int scan_blocks = (n_dst + 1023) / 1024;
    scan_bsum_kernel<<<scan_blocks, 256, 0, s2>>>(n_dst);
    scan_top_kernel<<<1, 128, 0, s2>>>(scan_blocks);
    scan_apply_kernel<<<scan_blocks, 256, 0, s2>>>(n_dst, E);
    permute_kernel<<<(E + 255) / 256, 256, 0, s2>>>(src_idx, dst_idx, E);
    cudaEventRecord(evJoin, s2);

    // Stream A: merged projections (Q, K fp32; V fp16).
    int blocks_q = (n_dst + 63) / 64;
    int blocks_k = (n_src + 63) / 64;
    int blocks_v = (n_src + 63) / 64;
    proj3_kernel<<<blocks_q + blocks_k + blocks_v, 256, PROJ_SMEM>>>(
        dst_feat, src_feat, Wq, bq, Wk, bk, Wv, bv, n_dst, n_src, blocks_q, blocks_k);

    // Join: attention needs Q/K/V and the sorted edge lists.
    cudaStreamWaitEvent(0, evJoin, 0);
    attn_kernel<<<(n_dst + 7) / 8, 256>>>(out, n_dst);
}

// round 15
// speedup vs baseline: 1.2311x; 1.0260x over previous
#include <cuda_runtime.h>
#include <cuda_fp16.h>
#include <math_constants.h>
#include <cstdint>

// Problem constants (match reference)
#define D         128
#define N_SRC_MAX 50000
#define N_DST_MAX 50000
#define E_MAX     1600000
#define INV_SCALE 0.25f          // 1/sqrt(128/8) = 1/4

// ---------------- scratch (no allocations allowed) ----------------
__device__ __align__(128) float  g_Q[N_DST_MAX * D];
__device__ __align__(128) __half g_Kh[N_SRC_MAX * D];
__device__ __align__(128) __half g_Vh[N_SRC_MAX * D];
__device__ __align__(128) int    g_count[N_DST_MAX];
__device__ __align__(128) int    g_start[N_DST_MAX + 1];
__device__ __align__(128) int    g_cursor[N_DST_MAX];
__device__ __align__(128) int    g_perm_src[E_MAX];
__device__ __align__(128) int    g_bsum[128];
__device__ int g_is64;

// ---------------- helpers ----------------
__device__ __forceinline__ int load_idx(const void* p, int i) {
    if (g_is64) return (int)((const long long*)p)[i];
    return ((const int*)p)[i];
}
__device__ __forceinline__ void fma2(unsigned long long& d,
                                     unsigned long long a, unsigned long long b) {
    asm("fma.rn.f32x2 %0, %1, %2, %0;" : "+l"(d) : "l"(a), "l"(b));
}
__device__ __forceinline__ unsigned long long pack2(float x) {
    unsigned long long r;
    asm("mov.b64 %0, {%1, %1};" : "=l"(r) : "f"(x));
    return r;
}

// ---------------- dtype detection ----------------
__global__ void detect_idx_kernel(const void* src_idx, const void* dst_idx,
                                  int n_src, int n_dst, int E) {
    if (threadIdx.x == 0) g_is64 = 1;
    __syncthreads();
    int i = threadIdx.x;
    int limit = (E / 2 < 64) ? E / 2 : 64;
    if (i < limit) {
        long long s = ((const long long*)src_idx)[i];
        long long d = ((const long long*)dst_idx)[i];
        bool ok = (s >= 0 && s < n_src && d >= 0 && d < n_dst);
        if (!ok) atomicExch(&g_is64, 0);
    }
}

__global__ void zero_counts_kernel(int n_dst) {
    int i = blockIdx.x * blockDim.x + threadIdx.x;
    if (i < n_dst) g_count[i] = 0;
}

__global__ __launch_bounds__(256) void hist_kernel(const void* __restrict__ dst_idx, int E) {
    int i = blockIdx.x * blockDim.x + threadIdx.x;
    if (i < E) atomicAdd(&g_count[load_idx(dst_idx, i)], 1);
}

// ---------------- parallel exclusive scan (3 kernels) ----------------
__global__ __launch_bounds__(256) void scan_bsum_kernel(int n_dst) {
    int t = threadIdx.x;
    int base = blockIdx.x * 1024 + t * 4;
    int v = 0;
    #pragma unroll
    for (int j = 0; j < 4; j++) {
        int i = base + j;
        if (i < n_dst) v += g_count[i];
    }
    #pragma unroll
    for (int off = 16; off; off >>= 1) v += __shfl_xor_sync(0xFFFFFFFFu, v, off);
    __shared__ int ws[8];
    if ((t & 31) == 0) ws[t >> 5] = v;
    __syncthreads();
    if (t < 8) {
        int u = ws[t];
        #pragma unroll
        for (int off = 4; off; off >>= 1) u += __shfl_xor_sync(0xFFu, u, off);
        if (t == 0) g_bsum[blockIdx.x] = u;
    }
}

__global__ __launch_bounds__(128) void scan_top_kernel(int nblocks) {
    __shared__ int s[128];
    int t = threadIdx.x;
    s[t] = (t < nblocks) ? g_bsum[t] : 0;
    __syncthreads();
    for (int off = 1; off < 128; off <<= 1) {
        int v = (t >= off) ? s[t - off] : 0;
        __syncthreads();
        s[t] += v;
        __syncthreads();
    }
    int excl = (t == 0) ? 0 : s[t - 1];
    if (t < nblocks) g_bsum[t] = excl;
}

__global__ __launch_bounds__(256) void scan_apply_kernel(int n_dst, int E) {
    __shared__ int ws[8];
    int t = threadIdx.x;
    int lane = t & 31, wid = t >> 5;
    int base = blockIdx.x * 1024 + t * 4;
    int c[4];
    int s_local = 0;
    #pragma unroll
    for (int j = 0; j < 4; j++) {
        int i = base + j;
        c[j] = (i < n_dst) ? g_count[i] : 0;
        s_local += c[j];
    }
    int v = s_local;
    #pragma unroll
    for (int off = 1; off < 32; off <<= 1) {
        int u = __shfl_up_sync(0xFFFFFFFFu, v, off);
        if (lane >= off) v += u;
    }
    if (lane == 31) ws[wid] = v;
    __syncthreads();
    if (t < 8) {
        int u = ws[t];
        #pragma unroll
        for (int off = 1; off < 8; off <<= 1) {
            int x = __shfl_up_sync(0xFFu, u, off);
            if (t >= off) u += x;
        }
        ws[t] = u;
    }
    __syncthreads();
    int run = v - s_local + (wid ? ws[wid - 1] : 0) + g_bsum[blockIdx.x];
    #pragma unroll
    for (int j = 0; j < 4; j++) {
        int i = base + j;
        if (i < n_dst) {
            g_start[i]  = run;
            g_cursor[i] = run;
            run += c[j];
        }
    }
    if (blockIdx.x == 0 && t == 0) g_start[n_dst] = E;
}

__global__ __launch_bounds__(256) void permute_kernel(
    const void* __restrict__ src_idx, const void* __restrict__ dst_idx, int E)
{
    int i = blockIdx.x * blockDim.x + threadIdx.x;
    if (i < E) {
        int s = load_idx(src_idx, i);
        int d = load_idx(dst_idx, i);
        int pos = atomicAdd(&g_cursor[d], 1);
        g_perm_src[pos] = s;
    }
}

// ---------------- merged projection GEMM (FFMA2), all 3 matrices in one launch ----------------
// mode per block: Q -> fp32, K -> fp16, V -> fp16
#define XT_STRIDE 66
#define WT_STRIDE 132
#define PROJ_SMEM ((128 * XT_STRIDE + 128 * WT_STRIDE) * 4)
__global__ __launch_bounds__(256) void proj3_kernel(
    const float* __restrict__ dst_feat, const float* __restrict__ src_feat,
    const float* __restrict__ Wq, const float* __restrict__ bq_,
    const float* __restrict__ Wk, const float* __restrict__ bk_,
    const float* __restrict__ Wv, const float* __restrict__ bv_,
    int n_dst, int n_src, int blocks_q, int blocks_k)
{
    extern __shared__ float sm[];
    float* Xt = sm;                        // [128 k][66]
    float* Wt = sm + 128 * XT_STRIDE;      // [128 k][132]

    const int tid = threadIdx.x;
    const int bid = blockIdx.x;

    const float *X, *W, *B;
    int N, row0;
    int mode;                              // 0=Q(fp32), 1=K(fp16), 2=V(fp16)
    if (bid < blocks_q) {
        X = dst_feat; W = Wq; B = bq_; N = n_dst; row0 = bid * 64; mode = 0;
    } else if (bid < blocks_q + blocks_k) {
        X = src_feat; W = Wk; B = bk_; N = n_src; row0 = (bid - blocks_q) * 64; mode = 1;
    } else {
        X = src_feat; W = Wv; B = bv_; N = n_src; row0 = (bid - blocks_q - blocks_k) * 64; mode = 2;
    }

    #pragma unroll 4
    for (int idx = tid; idx < 128 * 128; idx += 256) {
        int o = idx >> 7, k = idx & 127;
        Wt[k * WT_STRIDE + o] = W[idx];
    }
    #pragma unroll
    for (int idx = tid; idx < 64 * 32; idx += 256) {
        int r = idx >> 5, c4 = idx & 31;
        int row = row0 + r;
        float4 v = (row < N) ? ((const float4*)X)[(size_t)row * 32 + c4]
                             : make_float4(0.f, 0.f, 0.f, 0.f);
        Xt[(c4 * 4 + 0) * XT_STRIDE + r] = v.x;
        Xt[(c4 * 4 + 1) * XT_STRIDE + r] = v.y;
        Xt[(c4 * 4 + 2) * XT_STRIDE + r] = v.z;
        Xt[(c4 * 4 + 3) * XT_STRIDE + r] = v.w;
    }
    __syncthreads();

    const int tcol = tid & 31;
    const int trow = tid >> 5;

    unsigned long long acc[4][4];
    #pragma unroll
    for (int p = 0; p < 4; p++)
        #pragma unroll
        for (int j = 0; j < 4; j++) acc[p][j] = 0ULL;

    #pragma unroll 4
    for (int k = 0; k < 128; k++) {
        float4 w = *(const float4*)&Wt[k * WT_STRIDE + tcol * 4];
        unsigned long long wp0 = pack2(w.x), wp1 = pack2(w.y),
                           wp2 = pack2(w.z), wp3 = pack2(w.w);
        const unsigned long long* xrow =
            (const unsigned long long*)&Xt[k * XT_STRIDE + trow * 8];
        #pragma unroll
        for (int p = 0; p < 4; p++) {
            unsigned long long xp = xrow[p];
            fma2(acc[p][0], xp, wp0);
            fma2(acc[p][1], xp, wp1);
            fma2(acc[p][2], xp, wp2);
            fma2(acc[p][3], xp, wp3);
        }
    }

    float4 bias = *(const float4*)&B[tcol * 4];
    __half* Hout = (mode == 1) ? g_Kh : g_Vh;
    #pragma unroll
    for (int p = 0; p < 4; p++) {
        float2 a0 = *(float2*)&acc[p][0];
        float2 a1 = *(float2*)&acc[p][1];
        float2 a2 = *(float2*)&acc[p][2];
        float2 a3 = *(float2*)&acc[p][3];
        int row_e = row0 + trow * 8 + 2 * p;
        float4 oe = make_float4(a0.x + bias.x, a1.x + bias.y, a2.x + bias.z, a3.x + bias.w);
        float4 oo = make_float4(a0.y + bias.x, a1.y + bias.y, a2.y + bias.z, a3.y + bias.w);
        if (mode != 0) {
            if (row_e < N) {
                __half2 h0 = __floats2half2_rn(oe.x, oe.y);
                __half2 h1 = __floats2half2_rn(oe.z, oe.w);
                uint2 u; u.x = *(uint32_t*)&h0; u.y = *(uint32_t*)&h1;
                ((uint2*)(Hout + (size_t)row_e * 128))[tcol] = u;
            }
            if (row_e + 1 < N) {
                __half2 h0 = __floats2half2_rn(oo.x, oo.y);
                __half2 h1 = __floats2half2_rn(oo.z, oo.w);
                uint2 u; u.x = *(uint32_t*)&h0; u.y = *(uint32_t*)&h1;
                ((uint2*)(Hout + (size_t)(row_e + 1) * 128))[tcol] = u;
            }
        } else {
            if (row_e < N)     ((float4*)g_Q)[(size_t)row_e * 32 + tcol] = oe;
            if (row_e + 1 < N) ((float4*)g_Q)[(size_t)(row_e + 1) * 32 + tcol] = oo;
        }
    }
}

// ---------------- fused attention: warp/dst, 4-edge unroll, fp16 K+V ----------------
__global__ __launch_bounds__(256) void attn_kernel(float* __restrict__ out, int n_dst)
{
    int w = (blockIdx.x * blockDim.x + threadIdx.x) >> 5;
    if (w >= n_dst) return;
    int lane = threadIdx.x & 31;

    int start = g_start[w];
    int end   = g_start[w + 1];

    float4 q = ((const float4*)(g_Q + (size_t)w * D))[lane];
    q.x *= INV_SCALE; q.y *= INV_SCALE; q.z *= INV_SCALE; q.w *= INV_SCALE;

    float m = -CUDART_INF_F;
    float denom = 0.0f;
    float4 acc = make_float4(0.f, 0.f, 0.f, 0.f);

    int p = start;
    for (; p + 4 <= end; p += 4) {
        int s0 = __ldg(&g_perm_src[p + 0]);
        int s1 = __ldg(&g_perm_src[p + 1]);
        int s2 = __ldg(&g_perm_src[p + 2]);
        int s3 = __ldg(&g_perm_src[p + 3]);

        uint2 kk0 = ((const uint2*)(g_Kh + (size_t)s0 * D))[lane];
        uint2 kk1 = ((const uint2*)(g_Kh + (size_t)s1 * D))[lane];
        uint2 kk2 = ((const uint2*)(g_Kh + (size_t)s2 * D))[lane];
        uint2 kk3 = ((const uint2*)(g_Kh + (size_t)s3 * D))[lane];
        uint2 u0 = ((const uint2*)(g_Vh + (size_t)s0 * D))[lane];
        uint2 u1 = ((const uint2*)(g_Vh + (size_t)s1 * D))[lane];
        uint2 u2 = ((const uint2*)(g_Vh + (size_t)s2 * D))[lane];
        uint2 u3 = ((const uint2*)(g_Vh + (size_t)s3 * D))[lane];

        float2 k0a = __half22float2(*(__half2*)&kk0.x), k0b = __half22float2(*(__half2*)&kk0.y);
        float2 k1a = __half22float2(*(__half2*)&kk1.x), k1b = __half22float2(*(__half2*)&kk1.y);
        float2 k2a = __half22float2(*(__half2*)&kk2.x), k2b = __half22float2(*(__half2*)&kk2.y);
        float2 k3a = __half22float2(*(__half2*)&kk3.x), k3b = __half22float2(*(__half2*)&kk3.y);

        float d0 = q.x * k0a.x + q.y * k0a.y + q.z * k0b.x + q.w * k0b.y;
        float d1 = q.x * k1a.x + q.y * k1a.y + q.z * k1b.x + q.w * k1b.y;
        float d2 = q.x * k2a.x + q.y * k2a.y + q.z * k2b.x + q.w * k2b.y;
        float d3 = q.x * k3a.x + q.y * k3a.y + q.z * k3b.x + q.w * k3b.y;

        #pragma unroll
        for (int off = 16; off > 0; off >>= 1) {
            d0 += __shfl_xor_sync(0xFFFFFFFFu, d0, off);
            d1 += __shfl_xor_sync(0xFFFFFFFFu, d1, off);
            d2 += __shfl_xor_sync(0xFFFFFFFFu, d2, off);
            d3 += __shfl_xor_sync(0xFFFFFFFFu, d3, off);
        }

        float m_new = fmaxf(m, fmaxf(fmaxf(d0, d1), fmaxf(d2, d3)));
        float scale = __expf(m - m_new);
        float w0 = __expf(d0 - m_new);
        float w1 = __expf(d1 - m_new);
        float w2 = __expf(d2 - m_new);
        float w3 = __expf(d3 - m_new);

        float2 v0a = __half22float2(*(__half2*)&u0.x), v0b = __half22float2(*(__half2*)&u0.y);
        float2 v1a = __half22float2(*(__half2*)&u1.x), v1b = __half22float2(*(__half2*)&u1.y);
        float2 v2a = __half22float2(*(__half2*)&u2.x), v2b = __half22float2(*(__half2*)&u2.y);
        float2 v3a = __half22float2(*(__half2*)&u3.x), v3b = __half22float2(*(__half2*)&u3.y);

        denom = denom * scale + ((w0 + w1) + (w2 + w3));
        acc.x = acc.x * scale + ((w0 * v0a.x + w1 * v1a.x) + (w2 * v2a.x + w3 * v3a.x));
        acc.y = acc.y * scale + ((w0 * v0a.y + w1 * v1a.y) + (w2 * v2a.y + w3 * v3a.y));
        acc.z = acc.z * scale + ((w0 * v0b.x + w1 * v1b.x) + (w2 * v2b.x + w3 * v3b.x));
        acc.w = acc.w * scale + ((w0 * v0b.y + w1 * v1b.y) + (w2 * v2b.y + w3 * v3b.y));
        m = m_new;
    }
    for (; p < end; ++p) {
        int s = __ldg(&g_perm_src[p]);
        uint2 kk = ((const uint2*)(g_Kh + (size_t)s * D))[lane];
        uint2 vv = ((const uint2*)(g_Vh + (size_t)s * D))[lane];
        float2 k01 = __half22float2(*(__half2*)&kk.x);
        float2 k23 = __half22float2(*(__half2*)&kk.y);
        float2 v01 = __half22float2(*(__half2*)&vv.x);
        float2 v23 = __half22float2(*(__half2*)&vv.y);

        float dot = q.x * k01.x + q.y * k01.y + q.z * k23.x + q.w * k23.y;
        #pragma unroll
        for (int off = 16; off > 0; off >>= 1)
            dot += __shfl_xor_sync(0xFFFFFFFFu, dot, off);

        float m_new = fmaxf(m, dot);
        float scale = __expf(m - m_new);
        float wgt   = __expf(dot - m_new);
        denom = denom * scale + wgt;
        acc.x = acc.x * scale + wgt * v01.x;
        acc.y = acc.y * scale + wgt * v01.y;
        acc.z = acc.z * scale + wgt * v23.x;
        acc.w = acc.w * scale + wgt * v23.y;
        m = m_new;
    }

    float inv = (denom > 0.0f) ? (1.0f / denom) : 0.0f;
    float4 r = make_float4(acc.x * inv, acc.y * inv, acc.z * inv, acc.w * inv);
    ((float4*)(out + (size_t)w * D))[lane] = r;
}

// ---------------- launch: fork-join two streams (R8 schedule) ----------------
extern "C" void kernel_launch(void* const* d_in, const int* in_sizes, int n_in,
                              void* d_out, int out_size)
{
    const float* src_feat = (const float*)d_in[0];
    const float* dst_feat = (const float*)d_in[1];
    const void*  src_idx  = d_in[2];
    const void*  dst_idx  = d_in[3];
    const float* Wq = (const float*)d_in[4];
    const float* bq = (const float*)d_in[5];
    const float* Wk = (const float*)d_in[6];
    const float* bk = (const float*)d_in[7];
    const float* Wv = (const float*)d_in[8];
    const float* bv = (const float*)d_in[9];
    float* out = (float*)d_out;

    int n_src = in_sizes[0] / D;
    int n_dst = in_sizes[1] / D;
    int E     = in_sizes[2];

    static cudaStream_t s2 = nullptr;
    static cudaEvent_t evFork = nullptr, evJoin = nullptr;
    static int attr_set = 0;
    if (!attr_set) {
        cudaFuncSetAttribute(proj3_kernel, cudaFuncAttributeMaxDynamicSharedMemorySize, PROJ_SMEM);
        cudaStreamCreateWithFlags(&s2, cudaStreamNonBlocking);
        cudaEventCreateWithFlags(&evFork, cudaEventDisableTiming);
        cudaEventCreateWithFlags(&evJoin, cudaEventDisableTiming);
        attr_set = 1;
    }

    // Fork: stream B handles the index/sort chain.
    cudaEventRecord(evFork, 0);
    cudaStreamWaitEvent(s2, evFork, 0);

    detect_idx_kernel<<<1, 64, 0, s2>>>(src_idx, dst_idx, n_src, n_dst, E);
    zero_counts_kernel<<<(n_dst + 255) / 256, 256, 0, s2>>>(n_dst);
    hist_kernel<<<(E + 255) / 256, 256, 0, s2>>>(dst_idx, E);
    int scan_blocks = (n_dst + 1023) / 1024;
    scan_bsum_kernel<<<scan_blocks, 256, 0, s2>>>(n_dst);
    scan_top_kernel<<<1, 128, 0, s2>>>(scan_blocks);
    scan_apply_kernel<<<scan_blocks, 256, 0, s2>>>(n_dst, E);
    permute_kernel<<<(E + 255) / 256, 256, 0, s2>>>(src_idx, dst_idx, E);
    cudaEventRecord(evJoin, s2);

    // Stream A: merged projections (Q fp32; K, V fp16).
    int blocks_q = (n_dst + 63) / 64;
    int blocks_k = (n_src + 63) / 64;
    int blocks_v = (n_src + 63) / 64;
    proj3_kernel<<<blocks_q + blocks_k + blocks_v, 256, PROJ_SMEM>>>(
        dst_feat, src_feat, Wq, bq, Wk, bk, Wv, bv, n_dst, n_src, blocks_q, blocks_k);

    // Join: attention needs Q/K/V and the sorted edge lists.
    cudaStreamWaitEvent(0, evJoin, 0);
    attn_kernel<<<(n_dst + 7) / 8, 256>>>(out, n_dst);
}

// round 16
// speedup vs baseline: 1.2325x; 1.0011x over previous
#include <cuda_runtime.h>
#include <cuda_fp16.h>
#include <math_constants.h>
#include <cstdint>

// Problem constants (match reference)
#define D         128
#define N_SRC_MAX 50000
#define N_DST_MAX 50000
#define E_MAX     1600000
#define INV_SCALE 0.25f          // 1/sqrt(128/8) = 1/4

// ---------------- scratch (no allocations allowed) ----------------
__device__ __align__(128) float  g_Q[N_DST_MAX * D];
// K/V interleaved fp16: per row 256 halfs = 32 groups of [k4g..k4g+3 | v4g..v4g+3]
__device__ __align__(128) __half g_KVh[N_SRC_MAX * 256];
__device__ __align__(128) int    g_count[N_DST_MAX];
__device__ __align__(128) int    g_start[N_DST_MAX + 1];
__device__ __align__(128) int    g_cursor[N_DST_MAX];
__device__ __align__(128) int    g_perm_src[E_MAX];
__device__ __align__(128) int    g_bsum[128];
__device__ int g_is64;

// ---------------- helpers ----------------
__device__ __forceinline__ int load_idx(const void* p, int i) {
    if (g_is64) return (int)((const long long*)p)[i];
    return ((const int*)p)[i];
}
__device__ __forceinline__ void fma2(unsigned long long& d,
                                     unsigned long long a, unsigned long long b) {
    asm("fma.rn.f32x2 %0, %1, %2, %0;" : "+l"(d) : "l"(a), "l"(b));
}
__device__ __forceinline__ unsigned long long pack2(float x) {
    unsigned long long r;
    asm("mov.b64 %0, {%1, %1};" : "=l"(r) : "f"(x));
    return r;
}

// ---------------- dtype detection ----------------
__global__ void detect_idx_kernel(const void* src_idx, const void* dst_idx,
                                  int n_src, int n_dst, int E) {
    if (threadIdx.x == 0) g_is64 = 1;
    __syncthreads();
    int i = threadIdx.x;
    int limit = (E / 2 < 64) ? E / 2 : 64;
    if (i < limit) {
        long long s = ((const long long*)src_idx)[i];
        long long d = ((const long long*)dst_idx)[i];
        bool ok = (s >= 0 && s < n_src && d >= 0 && d < n_dst);
        if (!ok) atomicExch(&g_is64, 0);
    }
}

__global__ void zero_counts_kernel(int n_dst) {
    int i = blockIdx.x * blockDim.x + threadIdx.x;
    if (i < n_dst) g_count[i] = 0;
}

__global__ __launch_bounds__(256) void hist_kernel(const void* __restrict__ dst_idx, int E) {
    int i = blockIdx.x * blockDim.x + threadIdx.x;
    if (i < E) atomicAdd(&g_count[load_idx(dst_idx, i)], 1);
}

// ---------------- parallel exclusive scan (3 kernels) ----------------
__global__ __launch_bounds__(256) void scan_bsum_kernel(int n_dst) {
    int t = threadIdx.x;
    int base = blockIdx.x * 1024 + t * 4;
    int v = 0;
    #pragma unroll
    for (int j = 0; j < 4; j++) {
        int i = base + j;
        if (i < n_dst) v += g_count[i];
    }
    #pragma unroll
    for (int off = 16; off; off >>= 1) v += __shfl_xor_sync(0xFFFFFFFFu, v, off);
    __shared__ int ws[8];
    if ((t & 31) == 0) ws[t >> 5] = v;
    __syncthreads();
    if (t < 8) {
        int u = ws[t];
        #pragma unroll
        for (int off = 4; off; off >>= 1) u += __shfl_xor_sync(0xFFu, u, off);
        if (t == 0) g_bsum[blockIdx.x] = u;
    }
}

__global__ __launch_bounds__(128) void scan_top_kernel(int nblocks) {
    __shared__ int s[128];
    int t = threadIdx.x;
    s[t] = (t < nblocks) ? g_bsum[t] : 0;
    __syncthreads();
    for (int off = 1; off < 128; off <<= 1) {
        int v = (t >= off) ? s[t - off] : 0;
        __syncthreads();
        s[t] += v;
        __syncthreads();
    }
    int excl = (t == 0) ? 0 : s[t - 1];
    if (t < nblocks) g_bsum[t] = excl;
}

__global__ __launch_bounds__(256) void scan_apply_kernel(int n_dst, int E) {
    __shared__ int ws[8];
    int t = threadIdx.x;
    int lane = t & 31, wid = t >> 5;
    int base = blockIdx.x * 1024 + t * 4;
    int c[4];
    int s_local = 0;
    #pragma unroll
    for (int j = 0; j < 4; j++) {
        int i = base + j;
        c[j] = (i < n_dst) ? g_count[i] : 0;
        s_local += c[j];
    }
    int v = s_local;
    #pragma unroll
    for (int off = 1; off < 32; off <<= 1) {
        int u = __shfl_up_sync(0xFFFFFFFFu, v, off);
        if (lane >= off) v += u;
    }
    if (lane == 31) ws[wid] = v;
    __syncthreads();
    if (t < 8) {
        int u = ws[t];
        #pragma unroll
        for (int off = 1; off < 8; off <<= 1) {
            int x = __shfl_up_sync(0xFFu, u, off);
            if (t >= off) u += x;
        }
        ws[t] = u;
    }
    __syncthreads();
    int run = v - s_local + (wid ? ws[wid - 1] : 0) + g_bsum[blockIdx.x];
    #pragma unroll
    for (int j = 0; j < 4; j++) {
        int i = base + j;
        if (i < n_dst) {
            g_start[i]  = run;
            g_cursor[i] = run;
            run += c[j];
        }
    }
    if (blockIdx.x == 0 && t == 0) g_start[n_dst] = E;
}

__global__ __launch_bounds__(256) void permute_kernel(
    const void* __restrict__ src_idx, const void* __restrict__ dst_idx, int E)
{
    int i = blockIdx.x * blockDim.x + threadIdx.x;
    if (i < E) {
        int s = load_idx(src_idx, i);
        int d = load_idx(dst_idx, i);
        int pos = atomicAdd(&g_cursor[d], 1);
        g_perm_src[pos] = s;
    }
}

// ---------------- merged projection GEMM (FFMA2), all 3 matrices in one launch ----------------
// mode per block: Q -> fp32, K -> fp16 (slot 0 of KV row), V -> fp16 (slot 1)
#define XT_STRIDE 66
#define WT_STRIDE 132
#define PROJ_SMEM ((128 * XT_STRIDE + 128 * WT_STRIDE) * 4)
__global__ __launch_bounds__(256) void proj3_kernel(
    const float* __restrict__ dst_feat, const float* __restrict__ src_feat,
    const float* __restrict__ Wq, const float* __restrict__ bq_,
    const float* __restrict__ Wk, const float* __restrict__ bk_,
    const float* __restrict__ Wv, const float* __restrict__ bv_,
    int n_dst, int n_src, int blocks_q, int blocks_k)
{
    extern __shared__ float sm[];
    float* Xt = sm;                        // [128 k][66]
    float* Wt = sm + 128 * XT_STRIDE;      // [128 k][132]

    const int tid = threadIdx.x;
    const int bid = blockIdx.x;

    const float *X, *W, *B;
    int N, row0;
    int mode;                              // 0=Q(fp32), 1=K(fp16 slot0), 2=V(fp16 slot1)
    if (bid < blocks_q) {
        X = dst_feat; W = Wq; B = bq_; N = n_dst; row0 = bid * 64; mode = 0;
    } else if (bid < blocks_q + blocks_k) {
        X = src_feat; W = Wk; B = bk_; N = n_src; row0 = (bid - blocks_q) * 64; mode = 1;
    } else {
        X = src_feat; W = Wv; B = bv_; N = n_src; row0 = (bid - blocks_q - blocks_k) * 64; mode = 2;
    }

    #pragma unroll 4
    for (int idx = tid; idx < 128 * 128; idx += 256) {
        int o = idx >> 7, k = idx & 127;
        Wt[k * WT_STRIDE + o] = W[idx];
    }
    #pragma unroll
    for (int idx = tid; idx < 64 * 32; idx += 256) {
        int r = idx >> 5, c4 = idx & 31;
        int row = row0 + r;
        float4 v = (row < N) ? ((const float4*)X)[(size_t)row * 32 + c4]
                             : make_float4(0.f, 0.f, 0.f, 0.f);
        Xt[(c4 * 4 + 0) * XT_STRIDE + r] = v.x;
        Xt[(c4 * 4 + 1) * XT_STRIDE + r] = v.y;
        Xt[(c4 * 4 + 2) * XT_STRIDE + r] = v.z;
        Xt[(c4 * 4 + 3) * XT_STRIDE + r] = v.w;
    }
    __syncthreads();

    const int tcol = tid & 31;
    const int trow = tid >> 5;

    unsigned long long acc[4][4];
    #pragma unroll
    for (int p = 0; p < 4; p++)
        #pragma unroll
        for (int j = 0; j < 4; j++) acc[p][j] = 0ULL;

    #pragma unroll 4
    for (int k = 0; k < 128; k++) {
        float4 w = *(const float4*)&Wt[k * WT_STRIDE + tcol * 4];
        unsigned long long wp0 = pack2(w.x), wp1 = pack2(w.y),
                           wp2 = pack2(w.z), wp3 = pack2(w.w);
        const unsigned long long* xrow =
            (const unsigned long long*)&Xt[k * XT_STRIDE + trow * 8];
        #pragma unroll
        for (int p = 0; p < 4; p++) {
            unsigned long long xp = xrow[p];
            fma2(acc[p][0], xp, wp0);
            fma2(acc[p][1], xp, wp1);
            fma2(acc[p][2], xp, wp2);
            fma2(acc[p][3], xp, wp3);
        }
    }

    float4 bias = *(const float4*)&B[tcol * 4];
    const int slot = mode - 1;   // 0 for K, 1 for V (mode!=0 only)
    #pragma unroll
    for (int p = 0; p < 4; p++) {
        float2 a0 = *(float2*)&acc[p][0];
        float2 a1 = *(float2*)&acc[p][1];
        float2 a2 = *(float2*)&acc[p][2];
        float2 a3 = *(float2*)&acc[p][3];
        int row_e = row0 + trow * 8 + 2 * p;
        float4 oe = make_float4(a0.x + bias.x, a1.x + bias.y, a2.x + bias.z, a3.x + bias.w);
        float4 oo = make_float4(a0.y + bias.x, a1.y + bias.y, a2.y + bias.z, a3.y + bias.w);
        if (mode != 0) {
            if (row_e < N) {
                __half2 h0 = __floats2half2_rn(oe.x, oe.y);
                __half2 h1 = __floats2half2_rn(oe.z, oe.w);
                uint2 u; u.x = *(uint32_t*)&h0; u.y = *(uint32_t*)&h1;
                ((uint2*)(g_KVh + (size_t)row_e * 256))[tcol * 2 + slot] = u;
            }
            if (row_e + 1 < N) {
                __half2 h0 = __floats2half2_rn(oo.x, oo.y);
                __half2 h1 = __floats2half2_rn(oo.z, oo.w);
                uint2 u; u.x = *(uint32_t*)&h0; u.y = *(uint32_t*)&h1;
                ((uint2*)(g_KVh + (size_t)(row_e + 1) * 256))[tcol * 2 + slot] = u;
            }
        } else {
            if (row_e < N)     ((float4*)g_Q)[(size_t)row_e * 32 + tcol] = oe;
            if (row_e + 1 < N) ((float4*)g_Q)[(size_t)(row_e + 1) * 32 + tcol] = oo;
        }
    }
}

// ---------------- fused attention: warp/dst, 4-edge unroll, fused KV LDG.128, idx prefetch ----
__global__ __launch_bounds__(256) void attn_kernel(float* __restrict__ out, int n_dst)
{
    int w = (blockIdx.x * blockDim.x + threadIdx.x) >> 5;
    if (w >= n_dst) return;
    int lane = threadIdx.x & 31;

    int start = g_start[w];
    int end   = g_start[w + 1];

    float4 q = ((const float4*)(g_Q + (size_t)w * D))[lane];
    q.x *= INV_SCALE; q.y *= INV_SCALE; q.z *= INV_SCALE; q.w *= INV_SCALE;

    float m = -CUDART_INF_F;
    float denom = 0.0f;
    float4 acc = make_float4(0.f, 0.f, 0.f, 0.f);

    const uint4* kv = (const uint4*)g_KVh;   // row stride = 32 uint4

    int p = start;
    int s0 = 0, s1 = 0, s2 = 0, s3 = 0;
    if (p + 4 <= end) {
        s0 = __ldg(&g_perm_src[p + 0]);
        s1 = __ldg(&g_perm_src[p + 1]);
        s2 = __ldg(&g_perm_src[p + 2]);
        s3 = __ldg(&g_perm_src[p + 3]);
    }
    for (; p + 4 <= end; ) {
        // gathers for current group (one LDG.128 per edge: k-chunk + v-chunk)
        uint4 a0 = __ldg(&kv[(size_t)s0 * 32 + lane]);
        uint4 a1 = __ldg(&kv[(size_t)s1 * 32 + lane]);
        uint4 a2 = __ldg(&kv[(size_t)s2 * 32 + lane]);
        uint4 a3 = __ldg(&kv[(size_t)s3 * 32 + lane]);

        // prefetch next group's indices (safe base if no next group)
        int pn = p + 4;
        int b  = (pn + 4 <= end) ? pn : p;
        int n0 = __ldg(&g_perm_src[b + 0]);
        int n1 = __ldg(&g_perm_src[b + 1]);
        int n2 = __ldg(&g_perm_src[b + 2]);
        int n3 = __ldg(&g_perm_src[b + 3]);

        float2 k0a = __half22float2(*(__half2*)&a0.x), k0b = __half22float2(*(__half2*)&a0.y);
        float2 k1a = __half22float2(*(__half2*)&a1.x), k1b = __half22float2(*(__half2*)&a1.y);
        float2 k2a = __half22float2(*(__half2*)&a2.x), k2b = __half22float2(*(__half2*)&a2.y);
        float2 k3a = __half22float2(*(__half2*)&a3.x), k3b = __half22float2(*(__half2*)&a3.y);

        float d0 = q.x * k0a.x + q.y * k0a.y + q.z * k0b.x + q.w * k0b.y;
        float d1 = q.x * k1a.x + q.y * k1a.y + q.z * k1b.x + q.w * k1b.y;
        float d2 = q.x * k2a.x + q.y * k2a.y + q.z * k2b.x + q.w * k2b.y;
        float d3 = q.x * k3a.x + q.y * k3a.y + q.z * k3b.x + q.w * k3b.y;

        #pragma unroll
        for (int off = 16; off > 0; off >>= 1) {
            d0 += __shfl_xor_sync(0xFFFFFFFFu, d0, off);
            d1 += __shfl_xor_sync(0xFFFFFFFFu, d1, off);
            d2 += __shfl_xor_sync(0xFFFFFFFFu, d2, off);
            d3 += __shfl_xor_sync(0xFFFFFFFFu, d3, off);
        }

        float m_new = fmaxf(m, fmaxf(fmaxf(d0, d1), fmaxf(d2, d3)));
        float scale = __expf(m - m_new);
        float w0 = __expf(d0 - m_new);
        float w1 = __expf(d1 - m_new);
        float w2 = __expf(d2 - m_new);
        float w3 = __expf(d3 - m_new);

        float2 v0a = __half22float2(*(__half2*)&a0.z), v0b = __half22float2(*(__half2*)&a0.w);
        float2 v1a = __half22float2(*(__half2*)&a1.z), v1b = __half22float2(*(__half2*)&a1.w);
        float2 v2a = __half22float2(*(__half2*)&a2.z), v2b = __half22float2(*(__half2*)&a2.w);
        float2 v3a = __half22float2(*(__half2*)&a3.z), v3b = __half22float2(*(__half2*)&a3.w);

        denom = denom * scale + ((w0 + w1) + (w2 + w3));
        acc.x = acc.x * scale + ((w0 * v0a.x + w1 * v1a.x) + (w2 * v2a.x + w3 * v3a.x));
        acc.y = acc.y * scale + ((w0 * v0a.y + w1 * v1a.y) + (w2 * v2a.y + w3 * v3a.y));
        acc.z = acc.z * scale + ((w0 * v0b.x + w1 * v1b.x) + (w2 * v2b.x + w3 * v3b.x));
        acc.w = acc.w * scale + ((w0 * v0b.y + w1 * v1b.y) + (w2 * v2b.y + w3 * v3b.y));
        m = m_new;

        s0 = n0; s1 = n1; s2 = n2; s3 = n3;
        p = pn;
    }
    // tail
    for (; p < end; ++p) {
        int s = __ldg(&g_perm_src[p]);
        uint4 a = __ldg(&kv[(size_t)s * 32 + lane]);
        float2 k01 = __half22float2(*(__half2*)&a.x);
        float2 k23 = __half22float2(*(__half2*)&a.y);
        float2 v01 = __half22float2(*(__half2*)&a.z);
        float2 v23 = __half22float2(*(__half2*)&a.w);

        float dot = q.x * k01.x + q.y * k01.y + q.z * k23.x + q.w * k23.y;
        #pragma unroll
        for (int off = 16; off > 0; off >>= 1)
            dot += __shfl_xor_sync(0xFFFFFFFFu, dot, off);

        float m_new = fmaxf(m, dot);
        float scale = __expf(m - m_new);
        float wgt   = __expf(dot - m_new);
        denom = denom * scale + wgt;
        acc.x = acc.x * scale + wgt * v01.x;
        acc.y = acc.y * scale + wgt * v01.y;
        acc.z = acc.z * scale + wgt * v23.x;
        acc.w = acc.w * scale + wgt * v23.y;
        m = m_new;
    }

    float inv = (denom > 0.0f) ? (1.0f / denom) : 0.0f;
    float4 r = make_float4(acc.x * inv, acc.y * inv, acc.z * inv, acc.w * inv);
    ((float4*)(out + (size_t)w * D))[lane] = r;
}

// ---------------- launch: fork-join two streams (R8 schedule) ----------------
extern "C" void kernel_launch(void* const* d_in, const int* in_sizes, int n_in,
                              void* d_out, int out_size)
{
    const float* src_feat = (const float*)d_in[0];
    const float* dst_feat = (const float*)d_in[1];
    const void*  src_idx  = d_in[2];
    const void*  dst_idx  = d_in[3];
    const float* Wq = (const float*)d_in[4];
    const float* bq = (const float*)d_in[5];
    const float* Wk = (const float*)d_in[6];
    const float* bk = (const float*)d_in[7];
    const float* Wv = (const float*)d_in[8];
    const float* bv = (const float*)d_in[9];
    float* out = (float*)d_out;

    int n_src = in_sizes[0] / D;
    int n_dst = in_sizes[1] / D;
    int E     = in_sizes[2];

    static cudaStream_t s2 = nullptr;
    static cudaEvent_t evFork = nullptr, evJoin = nullptr;
    static int attr_set = 0;
    if (!attr_set) {
        cudaFuncSetAttribute(proj3_kernel, cudaFuncAttributeMaxDynamicSharedMemorySize, PROJ_SMEM);
        cudaStreamCreateWithFlags(&s2, cudaStreamNonBlocking);
        cudaEventCreateWithFlags(&evFork, cudaEventDisableTiming);
        cudaEventCreateWithFlags(&evJoin, cudaEventDisableTiming);
        attr_set = 1;
    }

    // Fork: stream B handles the index/sort chain.
    cudaEventRecord(evFork, 0);
    cudaStreamWaitEvent(s2, evFork, 0);

    detect_idx_kernel<<<1, 64, 0, s2>>>(src_idx, dst_idx, n_src, n_dst, E);
    zero_counts_kernel<<<(n_dst + 255) / 256, 256, 0, s2>>>(n_dst);
    hist_kernel<<<(E + 255) / 256, 256, 0, s2>>>(dst_idx, E);
    int scan_blocks = (n_dst + 1023) / 1024;
    scan_bsum_kernel<<<scan_blocks, 256, 0, s2>>>(n_dst);
    scan_top_kernel<<<1, 128, 0, s2>>>(scan_blocks);
    scan_apply_kernel<<<scan_blocks, 256, 0, s2>>>(n_dst, E);
    permute_kernel<<<(E + 255) / 256, 256, 0, s2>>>(src_idx, dst_idx, E);
    cudaEventRecord(evJoin, s2);

    // Stream A: merged projections (Q fp32; K/V fp16 interleaved).
    int blocks_q = (n_dst + 63) / 64;
    int blocks_k = (n_src + 63) / 64;
    int blocks_v = (n_src + 63) / 64;
    proj3_kernel<<<blocks_q + blocks_k + blocks_v, 256, PROJ_SMEM>>>(
        dst_feat, src_feat, Wq, bq, Wk, bk, Wv, bv, n_dst, n_src, blocks_q, blocks_k);

    // Join: attention needs Q/KV and the sorted edge lists.
    cudaStreamWaitEvent(0, evJoin, 0);
    attn_kernel<<<(n_dst + 7) / 8, 256>>>(out, n_dst);
}

// round 17
// speedup vs baseline: 1.3040x; 1.0581x over previous
#include <cuda_runtime.h>
#include <cuda_fp16.h>
#include <math_constants.h>
#include <cstdint>

// Problem constants (match reference)
#define D         128
#define N_SRC_MAX 50000
#define N_DST_MAX 50000
#define E_MAX     1600000
#define INV_SCALE 0.25f          // 1/sqrt(128/8) = 1/4

// ---------------- scratch (no allocations allowed) ----------------
__device__ __align__(128) float  g_Q[N_DST_MAX * D];
// K/V interleaved fp16: per row 256 halfs = 32 groups of [k4g..4g+3 | v4g..4g+3]
__device__ __align__(128) __half g_KVh[N_SRC_MAX * 256];
__device__ __align__(128) int    g_count[N_DST_MAX];
__device__ __align__(128) int    g_start[N_DST_MAX + 1];
__device__ __align__(128) int    g_cursor[N_DST_MAX];
__device__ __align__(128) int    g_perm_src[E_MAX];
__device__ __align__(128) int    g_bsum[128];
__device__ int g_is64;

// ---------------- helpers ----------------
__device__ __forceinline__ int load_idx(const void* p, int i) {
    if (g_is64) return (int)((const long long*)p)[i];
    return ((const int*)p)[i];
}
__device__ __forceinline__ void fma2(unsigned long long& d,
                                     unsigned long long a, unsigned long long b) {
    asm("fma.rn.f32x2 %0, %1, %2, %0;" : "+l"(d) : "l"(a), "l"(b));
}

// ---------------- dtype detection ----------------
__global__ void detect_idx_kernel(const void* src_idx, const void* dst_idx,
                                  int n_src, int n_dst, int E) {
    if (threadIdx.x == 0) g_is64 = 1;
    __syncthreads();
    int i = threadIdx.x;
    int limit = (E / 2 < 64) ? E / 2 : 64;
    if (i < limit) {
        long long s = ((const long long*)src_idx)[i];
        long long d = ((const long long*)dst_idx)[i];
        bool ok = (s >= 0 && s < n_src && d >= 0 && d < n_dst);
        if (!ok) atomicExch(&g_is64, 0);
    }
}

__global__ void zero_counts_kernel(int n_dst) {
    int i = blockIdx.x * blockDim.x + threadIdx.x;
    if (i < n_dst) g_count[i] = 0;
}

__global__ __launch_bounds__(256) void hist_kernel(const void* __restrict__ dst_idx, int E) {
    int i = blockIdx.x * blockDim.x + threadIdx.x;
    if (i < E) atomicAdd(&g_count[load_idx(dst_idx, i)], 1);
}

// ---------------- parallel exclusive scan (3 kernels) ----------------
__global__ __launch_bounds__(256) void scan_bsum_kernel(int n_dst) {
    int t = threadIdx.x;
    int base = blockIdx.x * 1024 + t * 4;
    int v = 0;
    #pragma unroll
    for (int j = 0; j < 4; j++) {
        int i = base + j;
        if (i < n_dst) v += g_count[i];
    }
    #pragma unroll
    for (int off = 16; off; off >>= 1) v += __shfl_xor_sync(0xFFFFFFFFu, v, off);
    __shared__ int ws[8];
    if ((t & 31) == 0) ws[t >> 5] = v;
    __syncthreads();
    if (t < 8) {
        int u = ws[t];
        #pragma unroll
        for (int off = 4; off; off >>= 1) u += __shfl_xor_sync(0xFFu, u, off);
        if (t == 0) g_bsum[blockIdx.x] = u;
    }
}

__global__ __launch_bounds__(128) void scan_top_kernel(int nblocks) {
    __shared__ int s[128];
    int t = threadIdx.x;
    s[t] = (t < nblocks) ? g_bsum[t] : 0;
    __syncthreads();
    for (int off = 1; off < 128; off <<= 1) {
        int v = (t >= off) ? s[t - off] : 0;
        __syncthreads();
        s[t] += v;
        __syncthreads();
    }
    int excl = (t == 0) ? 0 : s[t - 1];
    if (t < nblocks) g_bsum[t] = excl;
}

__global__ __launch_bounds__(256) void scan_apply_kernel(int n_dst, int E) {
    __shared__ int ws[8];
    int t = threadIdx.x;
    int lane = t & 31, wid = t >> 5;
    int base = blockIdx.x * 1024 + t * 4;
    int c[4];
    int s_local = 0;
    #pragma unroll
    for (int j = 0; j < 4; j++) {
        int i = base + j;
        c[j] = (i < n_dst) ? g_count[i] : 0;
        s_local += c[j];
    }
    int v = s_local;
    #pragma unroll
    for (int off = 1; off < 32; off <<= 1) {
        int u = __shfl_up_sync(0xFFFFFFFFu, v, off);
        if (lane >= off) v += u;
    }
    if (lane == 31) ws[wid] = v;
    __syncthreads();
    if (t < 8) {
        int u = ws[t];
        #pragma unroll
        for (int off = 1; off < 8; off <<= 1) {
            int x = __shfl_up_sync(0xFFu, u, off);
            if (t >= off) u += x;
        }
        ws[t] = u;
    }
    __syncthreads();
    int run = v - s_local + (wid ? ws[wid - 1] : 0) + g_bsum[blockIdx.x];
    #pragma unroll
    for (int j = 0; j < 4; j++) {
        int i = base + j;
        if (i < n_dst) {
            g_start[i]  = run;
            g_cursor[i] = run;
            run += c[j];
        }
    }
    if (blockIdx.x == 0 && t == 0) g_start[n_dst] = E;
}

__global__ __launch_bounds__(256) void permute_kernel(
    const void* __restrict__ src_idx, const void* __restrict__ dst_idx, int E)
{
    int i = blockIdx.x * blockDim.x + threadIdx.x;
    if (i < E) {
        int s = load_idx(src_idx, i);
        int d = load_idx(dst_idx, i);
        int pos = atomicAdd(&g_cursor[d], 1);
        g_perm_src[pos] = s;
    }
}

// ---------------- merged projection GEMM (FFMA2 packed over k-parity) ----------------
// No transposes: X and W both row-major in smem, conflict-free float2 fills.
// acc.lo accumulates even-k products, acc.hi odd-k; out = lo + hi.
// Columns per thread are tcol + 32j so w-load lane stride = 130 words (2-wavefront min).
#define XS_STRIDE 130
#define WS_STRIDE 130
#define PROJ_SMEM ((64 * XS_STRIDE + 128 * WS_STRIDE) * 4)   // 99840 B
__global__ __launch_bounds__(256) void proj3_kernel(
    const float* __restrict__ dst_feat, const float* __restrict__ src_feat,
    const float* __restrict__ Wq, const float* __restrict__ bq_,
    const float* __restrict__ Wk, const float* __restrict__ bk_,
    const float* __restrict__ Wv, const float* __restrict__ bv_,
    int n_dst, int n_src, int blocks_q, int blocks_k)
{
    extern __shared__ float sm[];
    float* Xs = sm;                        // [64 rows][130] row-major
    float* Ws = sm + 64 * XS_STRIDE;       // [128 cols][130] row-major (k contiguous)

    const int tid = threadIdx.x;
    const int bid = blockIdx.x;

    const float *X, *W, *B;
    int N, row0;
    int mode;                              // 0=Q(fp32), 1=K(fp16 slot0), 2=V(fp16 slot1)
    if (bid < blocks_q) {
        X = dst_feat; W = Wq; B = bq_; N = n_dst; row0 = bid * 64; mode = 0;
    } else if (bid < blocks_q + blocks_k) {
        X = src_feat; W = Wk; B = bk_; N = n_src; row0 = (bid - blocks_q) * 64; mode = 1;
    } else {
        X = src_feat; W = Wv; B = bv_; N = n_src; row0 = (bid - blocks_q - blocks_k) * 64; mode = 2;
    }

    // W fill: straight float2 copy (coalesced LDG.64, conflict-free STS.64)
    #pragma unroll 8
    for (int idx = tid; idx < 128 * 64; idx += 256) {
        int o = idx >> 6, k2 = idx & 63;
        *(float2*)&Ws[o * WS_STRIDE + k2 * 2] = ((const float2*)W)[idx];
    }
    // X fill: row-major float2 copy (zero-pad OOB rows)
    #pragma unroll 4
    for (int idx = tid; idx < 64 * 64; idx += 256) {
        int r = idx >> 6, k2 = idx & 63;
        int row = row0 + r;
        float2 v = (row < N) ? ((const float2*)X)[(size_t)row * 64 + k2]
                             : make_float2(0.f, 0.f);
        *(float2*)&Xs[r * XS_STRIDE + k2 * 2] = v;
    }
    __syncthreads();

    const int tcol = tid & 31;    // cols: tcol + 32j, j=0..3
    const int trow = tid >> 5;    // rows: trow*8 .. +7

    const float* xbase = &Xs[trow * 8 * XS_STRIDE];
    const float* wbase = &Ws[tcol * WS_STRIDE];

    unsigned long long acc[8][4];
    #pragma unroll
    for (int i = 0; i < 8; i++)
        #pragma unroll
        for (int j = 0; j < 4; j++) acc[i][j] = 0ULL;

    #pragma unroll 2
    for (int kp = 0; kp < 64; kp++) {
        unsigned long long w0 = *(const unsigned long long*)&wbase[ 0 * WS_STRIDE + 2 * kp];
        unsigned long long w1 = *(const unsigned long long*)&wbase[32 * WS_STRIDE + 2 * kp];
        unsigned long long w2 = *(const unsigned long long*)&wbase[64 * WS_STRIDE + 2 * kp];
        unsigned long long w3 = *(const unsigned long long*)&wbase[96 * WS_STRIDE + 2 * kp];
        #pragma unroll
        for (int i = 0; i < 8; i++) {
            unsigned long long x = *(const unsigned long long*)&xbase[i * XS_STRIDE + 2 * kp];
            fma2(acc[i][0], x, w0);
            fma2(acc[i][1], x, w1);
            fma2(acc[i][2], x, w2);
            fma2(acc[i][3], x, w3);
        }
    }

    float bj[4];
    #pragma unroll
    for (int j = 0; j < 4; j++) bj[j] = __ldg(&B[tcol + 32 * j]);

    const int slot = mode - 1;   // 0 for K, 1 for V (mode != 0 only)
    #pragma unroll
    for (int i = 0; i < 8; i++) {
        int row = row0 + trow * 8 + i;
        if (row >= N) continue;
        #pragma unroll
        for (int j = 0; j < 4; j++) {
            float2 a = *(float2*)&acc[i][j];
            float val = a.x + a.y + bj[j];
            int c = tcol + 32 * j;
            if (mode == 0) {
                g_Q[(size_t)row * 128 + c] = val;
            } else {
                int g = c >> 2;
                g_KVh[(size_t)row * 256 + g * 8 + slot * 4 + (c & 3)] = __float2half_rn(val);
            }
        }
    }
}

// ---------------- fused attention: warp/dst, 4-edge unroll, fused KV LDG.128, idx prefetch ----
__global__ __launch_bounds__(256) void attn_kernel(float* __restrict__ out, int n_dst)
{
    int w = (blockIdx.x * blockDim.x + threadIdx.x) >> 5;
    if (w >= n_dst) return;
    int lane = threadIdx.x & 31;

    int start = g_start[w];
    int end   = g_start[w + 1];

    float4 q = ((const float4*)(g_Q + (size_t)w * D))[lane];
    q.x *= INV_SCALE; q.y *= INV_SCALE; q.z *= INV_SCALE; q.w *= INV_SCALE;

    float m = -CUDART_INF_F;
    float denom = 0.0f;
    float4 acc = make_float4(0.f, 0.f, 0.f, 0.f);

    const uint4* kv = (const uint4*)g_KVh;   // row stride = 32 uint4

    int p = start;
    int s0 = 0, s1 = 0, s2 = 0, s3 = 0;
    if (p + 4 <= end) {
        s0 = __ldg(&g_perm_src[p + 0]);
        s1 = __ldg(&g_perm_src[p + 1]);
        s2 = __ldg(&g_perm_src[p + 2]);
        s3 = __ldg(&g_perm_src[p + 3]);
    }
    for (; p + 4 <= end; ) {
        uint4 a0 = __ldg(&kv[(size_t)s0 * 32 + lane]);
        uint4 a1 = __ldg(&kv[(size_t)s1 * 32 + lane]);
        uint4 a2 = __ldg(&kv[(size_t)s2 * 32 + lane]);
        uint4 a3 = __ldg(&kv[(size_t)s3 * 32 + lane]);

        int pn = p + 4;
        int b  = (pn + 4 <= end) ? pn : p;
        int n0 = __ldg(&g_perm_src[b + 0]);
        int n1 = __ldg(&g_perm_src[b + 1]);
        int n2 = __ldg(&g_perm_src[b + 2]);
        int n3 = __ldg(&g_perm_src[b + 3]);

        float2 k0a = __half22float2(*(__half2*)&a0.x), k0b = __half22float2(*(__half2*)&a0.y);
        float2 k1a = __half22float2(*(__half2*)&a1.x), k1b = __half22float2(*(__half2*)&a1.y);
        float2 k2a = __half22float2(*(__half2*)&a2.x), k2b = __half22float2(*(__half2*)&a2.y);
        float2 k3a = __half22float2(*(__half2*)&a3.x), k3b = __half22float2(*(__half2*)&a3.y);

        float d0 = q.x * k0a.x + q.y * k0a.y + q.z * k0b.x + q.w * k0b.y;
        float d1 = q.x * k1a.x + q.y * k1a.y + q.z * k1b.x + q.w * k1b.y;
        float d2 = q.x * k2a.x + q.y * k2a.y + q.z * k2b.x + q.w * k2b.y;
        float d3 = q.x * k3a.x + q.y * k3a.y + q.z * k3b.x + q.w * k3b.y;

        #pragma unroll
        for (int off = 16; off > 0; off >>= 1) {
            d0 += __shfl_xor_sync(0xFFFFFFFFu, d0, off);
            d1 += __shfl_xor_sync(0xFFFFFFFFu, d1, off);
            d2 += __shfl_xor_sync(0xFFFFFFFFu, d2, off);
            d3 += __shfl_xor_sync(0xFFFFFFFFu, d3, off);
        }

        float m_new = fmaxf(m, fmaxf(fmaxf(d0, d1), fmaxf(d2, d3)));
        float scale = __expf(m - m_new);
        float w0 = __expf(d0 - m_new);
        float w1 = __expf(d1 - m_new);
        float w2 = __expf(d2 - m_new);
        float w3 = __expf(d3 - m_new);

        float2 v0a = __half22float2(*(__half2*)&a0.z), v0b = __half22float2(*(__half2*)&a0.w);
        float2 v1a = __half22float2(*(__half2*)&a1.z), v1b = __half22float2(*(__half2*)&a1.w);
        float2 v2a = __half22float2(*(__half2*)&a2.z), v2b = __half22float2(*(__half2*)&a2.w);
        float2 v3a = __half22float2(*(__half2*)&a3.z), v3b = __half22float2(*(__half2*)&a3.w);

        denom = denom * scale + ((w0 + w1) + (w2 + w3));
        acc.x = acc.x * scale + ((w0 * v0a.x + w1 * v1a.x) + (w2 * v2a.x + w3 * v3a.x));
        acc.y = acc.y * scale + ((w0 * v0a.y + w1 * v1a.y) + (w2 * v2a.y + w3 * v3a.y));
        acc.z = acc.z * scale + ((w0 * v0b.x + w1 * v1b.x) + (w2 * v2b.x + w3 * v3b.x));
        acc.w = acc.w * scale + ((w0 * v0b.y + w1 * v1b.y) + (w2 * v2b.y + w3 * v3b.y));
        m = m_new;

        s0 = n0; s1 = n1; s2 = n2; s3 = n3;
        p = pn;
    }
    for (; p < end; ++p) {
        int s = __ldg(&g_perm_src[p]);
        uint4 a = __ldg(&kv[(size_t)s * 32 + lane]);
        float2 k01 = __half22float2(*(__half2*)&a.x);
        float2 k23 = __half22float2(*(__half2*)&a.y);
        float2 v01 = __half22float2(*(__half2*)&a.z);
        float2 v23 = __half22float2(*(__half2*)&a.w);

        float dot = q.x * k01.x + q.y * k01.y + q.z * k23.x + q.w * k23.y;
        #pragma unroll
        for (int off = 16; off > 0; off >>= 1)
            dot += __shfl_xor_sync(0xFFFFFFFFu, dot, off);

        float m_new = fmaxf(m, dot);
        float scale = __expf(m - m_new);
        float wgt   = __expf(dot - m_new);
        denom = denom * scale + wgt;
        acc.x = acc.x * scale + wgt * v01.x;
        acc.y = acc.y * scale + wgt * v01.y;
        acc.z = acc.z * scale + wgt * v23.x;
        acc.w = acc.w * scale + wgt * v23.y;
        m = m_new;
    }

    float inv = (denom > 0.0f) ? (1.0f / denom) : 0.0f;
    float4 r = make_float4(acc.x * inv, acc.y * inv, acc.z * inv, acc.w * inv);
    ((float4*)(out + (size_t)w * D))[lane] = r;
}

// ---------------- launch: fork-join two streams (R8 schedule) ----------------
extern "C" void kernel_launch(void* const* d_in, const int* in_sizes, int n_in,
                              void* d_out, int out_size)
{
    const float* src_feat = (const float*)d_in[0];
    const float* dst_feat = (const float*)d_in[1];
    const void*  src_idx  = d_in[2];
    const void*  dst_idx  = d_in[3];
    const float* Wq = (const float*)d_in[4];
    const float* bq = (const float*)d_in[5];
    const float* Wk = (const float*)d_in[6];
    const float* bk = (const float*)d_in[7];
    const float* Wv = (const float*)d_in[8];
    const float* bv = (const float*)d_in[9];
    float* out = (float*)d_out;

    int n_src = in_sizes[0] / D;
    int n_dst = in_sizes[1] / D;
    int E     = in_sizes[2];

    static cudaStream_t s2 = nullptr;
    static cudaEvent_t evFork = nullptr, evJoin = nullptr;
    static int attr_set = 0;
    if (!attr_set) {
        cudaFuncSetAttribute(proj3_kernel, cudaFuncAttributeMaxDynamicSharedMemorySize, PROJ_SMEM);
        cudaStreamCreateWithFlags(&s2, cudaStreamNonBlocking);
        cudaEventCreateWithFlags(&evFork, cudaEventDisableTiming);
        cudaEventCreateWithFlags(&evJoin, cudaEventDisableTiming);
        attr_set = 1;
    }

    // Fork: stream B handles the index/sort chain.
    cudaEventRecord(evFork, 0);
    cudaStreamWaitEvent(s2, evFork, 0);

    detect_idx_kernel<<<1, 64, 0, s2>>>(src_idx, dst_idx, n_src, n_dst, E);
    zero_counts_kernel<<<(n_dst + 255) / 256, 256, 0, s2>>>(n_dst);
    hist_kernel<<<(E + 255) / 256, 256, 0, s2>>>(dst_idx, E);
    int scan_blocks = (n_dst + 1023) / 1024;
    scan_bsum_kernel<<<scan_blocks, 256, 0, s2>>>(n_dst);
    scan_top_kernel<<<1, 128, 0, s2>>>(scan_blocks);
    scan_apply_kernel<<<scan_blocks, 256, 0, s2>>>(n_dst, E);
    permute_kernel<<<(E + 255) / 256, 256, 0, s2>>>(src_idx, dst_idx, E);
    cudaEventRecord(evJoin, s2);

    // Stream A: merged projections (Q fp32; K/V fp16 interleaved).
    int blocks_q = (n_dst + 63) / 64;
    int blocks_k = (n_src + 63) / 64;
    int blocks_v = (n_src + 63) / 64;
    proj3_kernel<<<blocks_q + blocks_k + blocks_v, 256, PROJ_SMEM>>>(
        dst_feat, src_feat, Wq, bq, Wk, bk, Wv, bv, n_dst, n_src, blocks_q, blocks_k);

    // Join: attention needs Q/KV and the sorted edge lists.
    cudaStreamWaitEvent(0, evJoin, 0);
    attn_kernel<<<(n_dst + 7) / 8, 256>>>(out, n_dst);
}